// round 1
// baseline (speedup 1.0000x reference)
#include <cuda_runtime.h>

// Problem constants (fixed by this dataset instance)
#define ITERS 5
#define NV 68      // base VNs
#define MC 46      // base CNs
#define ZL 384     // lifting size
#define NE 368     // edges
#define BB 64      // batch
#define MAXDEG 16  // max CN degree supported (actual = 8)

// Persistent scratch (no allocations allowed)
__device__ signed char g_extq[BB * NE * ZL];   // quantized C2V messages, value = 2*q in [-15,15], CN-domain z
__device__ float       g_tot [BB * NV * ZL];   // total beliefs, layout [b][n][z]
__device__ int g_cnptr[MC + 1];
__device__ int g_cpack[NE];   // CN-order: e | vn<<9 | shift<<16
__device__ int g_vnptr[NV + 1];
__device__ int g_vpack[NE];   // VN-order: e | shift<<16

// ---------------------------------------------------------------------------
// Setup: build CN-CSR and VN-CSR from edge lists (deterministic placement).
// ---------------------------------------------------------------------------
__global__ void k_setup(const int* __restrict__ evn, const int* __restrict__ ecn,
                        const int* __restrict__ esh) {
    __shared__ int s_vn[NE], s_cn[NE], s_sh[NE];
    __shared__ int ccnt[MC], vcnt[NV];
    __shared__ int cbase[MC], vbase[NV];
    int t = threadIdx.x;
    if (t < NE) { s_vn[t] = evn[t]; s_cn[t] = ecn[t]; s_sh[t] = esh[t]; }
    if (t < MC) ccnt[t] = 0;
    if (t < NV) vcnt[t] = 0;
    __syncthreads();
    if (t < NE) { atomicAdd(&ccnt[s_cn[t]], 1); atomicAdd(&vcnt[s_vn[t]], 1); }
    __syncthreads();
    if (t == 0) {
        int run = 0;
        for (int c = 0; c < MC; ++c) { cbase[c] = run; g_cnptr[c] = run; run += ccnt[c]; }
        g_cnptr[MC] = run;
        run = 0;
        for (int n = 0; n < NV; ++n) { vbase[n] = run; g_vnptr[n] = run; run += vcnt[n]; }
        g_vnptr[NV] = run;
    }
    __syncthreads();
    if (t < NE) {
        int c = s_cn[t], v = s_vn[t];
        int pc = 0, pv = 0;
        for (int e2 = 0; e2 < t; ++e2) {     // stable (e-ascending) position
            pc += (s_cn[e2] == c);
            pv += (s_vn[e2] == v);
        }
        g_cpack[cbase[c] + pc] = t | (v << 9) | (s_sh[t] << 16);
        g_vpack[vbase[v] + pv] = t | (s_sh[t] << 16);
    }
}

// ---------------------------------------------------------------------------
// VN update: tot[b][n][z] = ch + sum_{e in VN(n)} 0.5*extq[b][e][(z+shift)%Z].
// Also writes out[it-1][b][z][n] (== tot) via shared transpose when requested.
// ---------------------------------------------------------------------------
__global__ void k_vn(const float* __restrict__ xa, float* __restrict__ out_prev,
                     int use_state, int write_out) {
    __shared__ float s[NV][65];           // padded transpose buffer
    const int tid = threadIdx.x;          // 64 threads = one z-tile
    const int b = blockIdx.y;
    const int z0 = blockIdx.x * 64;
    const int z = z0 + tid;
    const signed char* __restrict__ eq = g_extq + (size_t)b * (NE * ZL);
    float* __restrict__ tb = g_tot + (size_t)b * (NV * ZL);

    for (int n = 0; n < NV; ++n) {
        float acc = xa[((size_t)b * NV + n) * ZL + z];
        if (use_state) {
            const int j1 = g_vnptr[n + 1];
            for (int j = g_vnptr[n]; j < j1; ++j) {
                const int pk = g_vpack[j];
                const int e = pk & 511;
                const int sh = pk >> 16;
                int zc = z + sh; if (zc >= ZL) zc -= ZL;
                acc += 0.5f * (float)eq[e * ZL + zc];
            }
        }
        tb[n * ZL + z] = acc;
        s[n][tid] = acc;
    }
    if (write_out) {
        __syncthreads();
        float* __restrict__ dst = out_prev + ((size_t)b * ZL + z0) * NV;
        for (int f = tid; f < 64 * NV; f += 64) {
            const int zl = f / NV;
            const int n = f - zl * NV;
            dst[f] = s[n][zl];
        }
    }
}

// ---------------------------------------------------------------------------
// CN update (min-sum with the reference's exact-tie semantics) + QMS quantize.
// Works entirely in the CN z-domain; state updated in place.
// ---------------------------------------------------------------------------
__global__ void k_cn(const float* __restrict__ cnw, int it, int first) {
    const int tid = threadIdx.x;          // 64 threads = one z-tile
    const int b = blockIdx.y;
    const int z = blockIdx.x * 64 + tid;
    const int c0 = blockIdx.z * (MC / 2);
    const int c1 = c0 + (MC / 2);
    const float w = cnw[it];
    const float* __restrict__ tb = g_tot + (size_t)b * (NV * ZL);
    signed char* __restrict__ eq = g_extq + (size_t)b * (NE * ZL);

    for (int c = c0; c < c1; ++c) {
        const int p0 = g_cnptr[c];
        const int deg = g_cnptr[c + 1] - p0;
        float mag[MAXDEG];
        unsigned neg = 0;
        float min1 = 1e30f;
#pragma unroll
        for (int j = 0; j < MAXDEG; ++j) {
            if (j < deg) {
                const int pk = g_cpack[p0 + j];
                const int e = pk & 511;
                const int vn = (pk >> 9) & 127;
                const int sh = pk >> 16;
                int zv = z - sh; if (zv < 0) zv += ZL;
                const float t = tb[vn * ZL + zv];
                const float c2v = first ? 0.f : 0.5f * (float)eq[e * ZL + z];
                const float v = fminf(fmaxf(t - c2v, -20.f), 20.f);
                const float m = fabsf(v);
                mag[j] = m;
                if (v < 0.f) neg |= (1u << j);
                min1 = fminf(min1, m);
            }
        }
        float min2 = 1e9f;   // BIG, matches reference when all mags tie
#pragma unroll
        for (int j = 0; j < MAXDEG; ++j)
            if (j < deg && mag[j] != min1) min2 = fminf(min2, mag[j]);
        const float cs = (__popc(neg) & 1) ? -1.f : 1.f;
#pragma unroll
        for (int j = 0; j < MAXDEG; ++j) {
            if (j < deg) {
                const float em = (mag[j] == min1) ? min2 : min1;
                const float sg = ((neg >> j) & 1u) ? -cs : cs;
                const float x = w * sg * em;
                // QMS5 forward value: clip(round(2x)/2, -7.5, 7.5); rintf = round-half-even
                const float q = fminf(fmaxf(rintf(x + x) * 0.5f, -7.5f), 7.5f);
                const int e = g_cpack[p0 + j] & 511;
                eq[e * ZL + z] = (signed char)__float2int_rn(q + q);
            }
        }
    }
}

// ---------------------------------------------------------------------------
extern "C" void kernel_launch(void* const* d_in, const int* in_sizes, int n_in,
                              void* d_out, int out_size) {
    const float* xa  = (const float*)d_in[0];   // [B, N, Z] f32
    const float* cnw = (const float*)d_in[1];   // [ITERS] f32
    const int* evn   = (const int*)d_in[2];     // [E] i32
    const int* ecn   = (const int*)d_in[3];     // [E] i32
    const int* esh   = (const int*)d_in[4];     // [E] i32
    float* out = (float*)d_out;                 // [ITERS, B, Z, N] f32

    k_setup<<<1, 384>>>(evn, ecn, esh);

    dim3 gT(ZL / 64, BB);
    dim3 gC(ZL / 64, BB, 2);

    // Iteration 0 VN pass: tot = channel only (state unused)
    k_vn<<<gT, 64>>>(xa, nullptr, 0, 0);
    for (int it = 0; it < ITERS; ++it) {
        k_cn<<<gC, 64>>>(cnw, it, it == 0);
        // VN pass of iteration it+1 writes out[it] (== marginalized output of it)
        k_vn<<<gT, 64>>>(xa, out + (size_t)it * BB * ZL * NV, 1, 1);
    }
}

// round 2
// speedup vs baseline: 3.5580x; 3.5580x over previous
#include <cuda_runtime.h>

// Problem constants (fixed by this dataset instance)
#define ITERS 5
#define NV 68      // base VNs
#define MC 46      // base CNs
#define ZL 384     // lifting size
#define NE 368     // edges
#define BB 64      // batch
#define MAXDEG 8   // CN degree (E = M*8 exactly, per reference construction)

// Persistent scratch (no allocations allowed)
__device__ signed char g_extq[BB * NE * ZL];   // quantized C2V messages, value = 2*q in [-15,15], CN-domain z
__device__ float       g_tot [BB * NV * ZL];   // total beliefs, layout [b][n][z]
__device__ int g_cnptr[MC + 1];
__device__ int g_cpack[NE];   // CN-order: e | vn<<9 | shift<<16
__device__ int g_vnptr[NV + 1];
__device__ int g_vpack[NE];   // VN-order: e | shift<<16

// ---------------------------------------------------------------------------
// Setup: build CN-CSR and VN-CSR from edge lists (deterministic placement).
// ---------------------------------------------------------------------------
__global__ void k_setup(const int* __restrict__ evn, const int* __restrict__ ecn,
                        const int* __restrict__ esh) {
    __shared__ int s_vn[NE], s_cn[NE], s_sh[NE];
    __shared__ int ccnt[MC], vcnt[NV];
    __shared__ int cbase[MC], vbase[NV];
    int t = threadIdx.x;
    if (t < NE) { s_vn[t] = evn[t]; s_cn[t] = ecn[t]; s_sh[t] = esh[t]; }
    if (t < MC) ccnt[t] = 0;
    if (t < NV) vcnt[t] = 0;
    __syncthreads();
    if (t < NE) { atomicAdd(&ccnt[s_cn[t]], 1); atomicAdd(&vcnt[s_vn[t]], 1); }
    __syncthreads();
    if (t == 0) {
        int run = 0;
        for (int c = 0; c < MC; ++c) { cbase[c] = run; g_cnptr[c] = run; run += ccnt[c]; }
        g_cnptr[MC] = run;
        run = 0;
        for (int n = 0; n < NV; ++n) { vbase[n] = run; g_vnptr[n] = run; run += vcnt[n]; }
        g_vnptr[NV] = run;
    }
    __syncthreads();
    if (t < NE) {
        int c = s_cn[t], v = s_vn[t];
        int pc = 0, pv = 0;
        for (int e2 = 0; e2 < t; ++e2) {     // stable (e-ascending) position
            pc += (s_cn[e2] == c);
            pv += (s_vn[e2] == v);
        }
        g_cpack[cbase[c] + pc] = t | (v << 9) | (s_sh[t] << 16);
        g_vpack[vbase[v] + pv] = t | (s_sh[t] << 16);
    }
}

// ---------------------------------------------------------------------------
// VN update: tot[b][n][z] = ch + sum_{e in VN(n)} 0.5*extq[b][e][(z+shift)%Z].
// Block = (64 z, 8 n-groups). Also writes out[it-1][b][z][n] (== tot) via
// shared transpose when requested.
// ---------------------------------------------------------------------------
__global__ __launch_bounds__(512) void k_vn(const float* __restrict__ xa,
                                            float* __restrict__ out_prev,
                                            int use_state, int write_out,
                                            int write_tot) {
    __shared__ float s[NV][65];           // padded transpose buffer
    __shared__ int svptr[NV + 1];
    __shared__ int svpack[NE];
    const int tx = threadIdx.x;           // z within tile (64)
    const int ty = threadIdx.y;           // n-group (8)
    const int tid = ty * 64 + tx;
    const int b = blockIdx.y;
    const int z0 = blockIdx.x * 64;
    const int z = z0 + tx;

    if (tid < NV + 1) svptr[tid] = g_vnptr[tid];
    if (tid < NE) svpack[tid] = g_vpack[tid];
    __syncthreads();

    const signed char* __restrict__ eq = g_extq + (size_t)b * (NE * ZL);
    float* __restrict__ tb = g_tot + (size_t)b * (NV * ZL);

    for (int n = ty; n < NV; n += 8) {
        float acc = xa[((size_t)b * NV + n) * ZL + z];
        if (use_state) {
            const int j1 = svptr[n + 1];
            for (int j = svptr[n]; j < j1; ++j) {
                const int pk = svpack[j];
                const int e = pk & 511;
                const int sh = pk >> 16;
                int zc = z + sh; if (zc >= ZL) zc -= ZL;
                acc += 0.5f * (float)eq[e * ZL + zc];
            }
        }
        if (write_tot) tb[n * ZL + z] = acc;
        s[n][tx] = acc;
    }
    if (write_out) {
        __syncthreads();
        float* __restrict__ dst = out_prev + ((size_t)b * ZL + z0) * NV;
        for (int f = tid; f < 64 * NV; f += 512) {
            const int zl = f / NV;
            const int n = f - zl * NV;
            dst[f] = s[n][zl];
        }
    }
}

// ---------------------------------------------------------------------------
// CN update (min-sum with the reference's exact-tie semantics) + QMS quantize.
// One thread per (b, c, z). Block = (64 z, 8 c). State updated in place.
// ---------------------------------------------------------------------------
__global__ __launch_bounds__(512) void k_cn(const float* __restrict__ cnw,
                                            int it, int first) {
    __shared__ int scptr[MC + 1];
    __shared__ int scpack[NE];
    const int tx = threadIdx.x;           // z within tile (64)
    const int ty = threadIdx.y;           // c within group (8)
    const int tid = ty * 64 + tx;
    if (tid < MC + 1) scptr[tid] = g_cnptr[tid];
    if (tid < NE) scpack[tid] = g_cpack[tid];
    __syncthreads();

    const int b = blockIdx.y;
    const int z = blockIdx.x * 64 + tx;
    const int c = blockIdx.z * 8 + ty;
    if (c >= MC) return;
    const float w = __ldg(&cnw[it]);
    const float* __restrict__ tb = g_tot + (size_t)b * (NV * ZL);
    signed char* __restrict__ eq = g_extq + (size_t)b * (NE * ZL);

    const int p0 = scptr[c];
    const int deg = scptr[c + 1] - p0;
    float mag[MAXDEG];
    unsigned neg = 0;
    float min1 = 1e30f;
#pragma unroll
    for (int j = 0; j < MAXDEG; ++j) {
        if (j < deg) {
            const int pk = scpack[p0 + j];
            const int e = pk & 511;
            const int vn = (pk >> 9) & 127;
            const int sh = pk >> 16;
            int zv = z - sh; if (zv < 0) zv += ZL;
            const float t = tb[vn * ZL + zv];
            const float c2v = first ? 0.f : 0.5f * (float)eq[e * ZL + z];
            const float v = fminf(fmaxf(t - c2v, -20.f), 20.f);
            const float m = fabsf(v);
            mag[j] = m;
            if (v < 0.f) neg |= (1u << j);
            min1 = fminf(min1, m);
        }
    }
    float min2 = 1e9f;   // BIG, matches reference when all mags tie
#pragma unroll
    for (int j = 0; j < MAXDEG; ++j)
        if (j < deg && mag[j] != min1) min2 = fminf(min2, mag[j]);
    const float cs = (__popc(neg) & 1) ? -1.f : 1.f;
#pragma unroll
    for (int j = 0; j < MAXDEG; ++j) {
        if (j < deg) {
            const float em = (mag[j] == min1) ? min2 : min1;
            const float sg = ((neg >> j) & 1u) ? -cs : cs;
            const float x = w * sg * em;
            // QMS5 forward value: clip(round(2x)/2, -7.5, 7.5); rintf = round-half-even
            const float q = fminf(fmaxf(rintf(x + x) * 0.5f, -7.5f), 7.5f);
            const int e = scpack[p0 + j] & 511;
            eq[e * ZL + z] = (signed char)__float2int_rn(q + q);
        }
    }
}

// ---------------------------------------------------------------------------
extern "C" void kernel_launch(void* const* d_in, const int* in_sizes, int n_in,
                              void* d_out, int out_size) {
    const float* xa  = (const float*)d_in[0];   // [B, N, Z] f32
    const float* cnw = (const float*)d_in[1];   // [ITERS] f32
    const int* evn   = (const int*)d_in[2];     // [E] i32
    const int* ecn   = (const int*)d_in[3];     // [E] i32
    const int* esh   = (const int*)d_in[4];     // [E] i32
    float* out = (float*)d_out;                 // [ITERS, B, Z, N] f32

    k_setup<<<1, 384>>>(evn, ecn, esh);

    dim3 blk(64, 8);
    dim3 gV(ZL / 64, BB);           // k_vn: (z-tile, batch)
    dim3 gC(ZL / 64, BB, 6);        // k_cn: (z-tile, batch, c-group of 8)

    // Iteration 0 VN pass: tot = channel only (state unused)
    k_vn<<<gV, blk>>>(xa, nullptr, 0, 0, 1);
    for (int it = 0; it < ITERS; ++it) {
        k_cn<<<gC, blk>>>(cnw, it, it == 0);
        // VN pass of iteration it+1 writes out[it] (== marginalized output of it);
        // the last one needs no tot for a subsequent CN pass.
        k_vn<<<gV, blk>>>(xa, out + (size_t)it * BB * ZL * NV, 1, 1,
                          it != ITERS - 1);
    }
}

// round 5
// speedup vs baseline: 4.0463x; 1.1372x over previous
#include <cuda_runtime.h>

// Problem constants (fixed by this dataset instance)
#define ITERS 5
#define NV 68      // base VNs
#define MC 46      // base CNs
#define ZL 384     // lifting size
#define NE 368     // edges
#define BB 64      // batch
#define ZW (ZL/4)  // 96 words per edge row

// Persistent scratch (no allocations allowed)
__device__ __align__(16) signed char g_extq[BB * NE * ZL]; // quantized C2V, value = 2*q in [-15,15]
__device__ __align__(16) float       g_tot [BB * NV * ZL]; // total beliefs, layout [b][n][z]
__device__ int g_cnptr[MC + 1];
__device__ int g_cpack[NE];   // CN-order: e | vn<<9 | shift<<16
__device__ int g_vnptr[NV + 1];
__device__ int g_vpack[NE];   // VN-order: e | shift<<16

// ---------------------------------------------------------------------------
// Setup: build CN-CSR and VN-CSR from edge lists (deterministic placement).
// ---------------------------------------------------------------------------
__global__ void k_setup(const int* __restrict__ evn, const int* __restrict__ ecn,
                        const int* __restrict__ esh) {
    __shared__ int s_vn[NE], s_cn[NE], s_sh[NE];
    __shared__ int ccnt[MC], vcnt[NV];
    __shared__ int cbase[MC], vbase[NV];
    int t = threadIdx.x;
    if (t < NE) { s_vn[t] = evn[t]; s_cn[t] = ecn[t]; s_sh[t] = esh[t]; }
    if (t < MC) ccnt[t] = 0;
    if (t < NV) vcnt[t] = 0;
    __syncthreads();
    if (t < NE) { atomicAdd(&ccnt[s_cn[t]], 1); atomicAdd(&vcnt[s_vn[t]], 1); }
    __syncthreads();
    if (t == 0) {
        int run = 0;
        for (int c = 0; c < MC; ++c) { cbase[c] = run; g_cnptr[c] = run; run += ccnt[c]; }
        g_cnptr[MC] = run;
        run = 0;
        for (int n = 0; n < NV; ++n) { vbase[n] = run; g_vnptr[n] = run; run += vcnt[n]; }
        g_vnptr[NV] = run;
    }
    __syncthreads();
    if (t < NE) {
        int c = s_cn[t], v = s_vn[t];
        int pc = 0, pv = 0;
        for (int e2 = 0; e2 < t; ++e2) {     // stable (e-ascending) position
            pc += (s_cn[e2] == c);
            pv += (s_vn[e2] == v);
        }
        g_cpack[cbase[c] + pc] = t | (v << 9) | (s_sh[t] << 16);
        g_vpack[vbase[v] + pv] = t | (s_sh[t] << 16);
    }
}

// ---------------------------------------------------------------------------
// VN update, z-quad per thread. Per edge: 2 aligned word loads + funnelshift,
// then guaranteed-semantics (signed char) extraction into int accumulators
// (exact: messages are 2*q in [-15,15], sums bounded far below 2^31).
// Block = (32 quads = 128 z, 16 n-groups). Writes tot (float4) and optionally
// the transposed output tile out[it-1][b][z][n] via shared.
// ---------------------------------------------------------------------------
__global__ __launch_bounds__(512) void k_vn(const float* __restrict__ xa,
                                            float* __restrict__ out_prev,
                                            int use_state, int write_out,
                                            int write_tot) {
    __shared__ __align__(16) float s[NV][132];   // float4-aligned padded rows
    __shared__ int svptr[NV + 1];
    __shared__ int svpack[NE];
    const int tx = threadIdx.x;           // quad within tile (32)
    const int ty = threadIdx.y;           // n-group (16)
    const int tid = ty * 32 + tx;
    const int b = blockIdx.y;
    const int q0 = blockIdx.x * 32;       // quad tile base
    const int q = q0 + tx;
    const int z4 = q * 4;

    for (int i = tid; i <= NV; i += 512) svptr[i] = g_vnptr[i];
    for (int i = tid; i < NE; i += 512) svpack[i] = g_vpack[i];
    __syncthreads();

    const signed char* __restrict__ eq = g_extq + (size_t)b * (NE * ZL);
    float* __restrict__ tb = g_tot + (size_t)b * (NV * ZL);

    for (int n = ty; n < NV; n += 16) {
        float4 ch = ((const float4*)xa)[((size_t)b * NV + n) * ZW + q];
        if (use_state) {
            int a0 = 0, a1 = 0, a2 = 0, a3 = 0;   // exact integer sums
            const int j1 = svptr[n + 1];
            for (int j = svptr[n]; j < j1; ++j) {
                const int pk = svpack[j];
                const int e = pk & 511;
                int zc = z4 + (pk >> 16); if (zc >= ZL) zc -= ZL;
                const unsigned* __restrict__ row = (const unsigned*)(eq + e * ZL);
                const int w0 = zc >> 2;
                int w1 = w0 + 1; if (w1 == ZW) w1 = 0;
                const unsigned u = __funnelshift_r(row[w0], row[w1], (zc & 3) * 8);
                a0 += (int)(signed char)(u);
                a1 += (int)(signed char)(u >> 8);
                a2 += (int)(signed char)(u >> 16);
                a3 += (int)(signed char)(u >> 24);
            }
            ch.x += 0.5f * (float)a0;
            ch.y += 0.5f * (float)a1;
            ch.z += 0.5f * (float)a2;
            ch.w += 0.5f * (float)a3;
        }
        if (write_tot) ((float4*)tb)[n * ZW + q] = ch;
        *(float4*)&s[n][tx * 4] = ch;
    }
    if (write_out) {
        __syncthreads();
        float4* __restrict__ dst = (float4*)(out_prev + ((size_t)b * ZL + q0 * 4) * NV);
        // 128 z-rows x 17 float4 per row (NV=68)
        for (int f = tid; f < 128 * 17; f += 512) {
            const int zl = f / 17;
            const int n0 = (f - zl * 17) * 4;
            float4 o;
            o.x = s[n0 + 0][zl]; o.y = s[n0 + 1][zl];
            o.z = s[n0 + 2][zl]; o.w = s[n0 + 3][zl];
            dst[f] = o;
        }
    }
}

// ---------------------------------------------------------------------------
// CN update (min-sum, reference-exact tie semantics) + QMS quantize.
// One thread per (b, c, z-quad). Aligned char4 state load/store.
// ---------------------------------------------------------------------------
__device__ __forceinline__ int qbyte(float vv, float mn1, float mn2, float csw) {
    const float em = (fabsf(vv) == mn1) ? mn2 : mn1;
    const float x = (vv < 0.f ? -csw : csw) * em;   // csw = +-w folded; sign flips exact
    float r = rintf(x + x);                          // round-half-even, matches jnp.round
    r = fminf(fmaxf(r, -15.f), 15.f);                // == clip(round(2x)/2,+-7.5) doubled
    return (int)r;
}

__global__ __launch_bounds__(256) void k_cn(const float* __restrict__ cnw,
                                            int it, int first) {
    __shared__ int scptr[MC + 1];
    __shared__ int scpack[NE];
    const int tx = threadIdx.x;           // quad (32)
    const int ty = threadIdx.y;           // c within group (8)
    const int tid = ty * 32 + tx;
    for (int i = tid; i <= MC; i += 256) scptr[i] = g_cnptr[i];
    for (int i = tid; i < NE; i += 256) scpack[i] = g_cpack[i];
    __syncthreads();

    const int b = blockIdx.y;
    const int z4 = (blockIdx.x * 32 + tx) * 4;
    const int c = blockIdx.z * 8 + ty;
    if (c >= MC) return;
    const float w = __ldg(&cnw[it]);
    const float* __restrict__ tb = g_tot + (size_t)b * (NV * ZL);
    signed char* __restrict__ eq = g_extq + (size_t)b * (NE * ZL);

    const int p0 = scptr[c];
    float4 v[8];
    unsigned negw = 0;                    // bit (k*8 + j): sign of edge j at z4+k
    float4 m1 = make_float4(1e30f, 1e30f, 1e30f, 1e30f);
#pragma unroll
    for (int j = 0; j < 8; ++j) {
        const int pk = scpack[p0 + j];
        const int e = pk & 511;
        const int vn = (pk >> 9) & 127;
        int zv = z4 - (pk >> 16); if (zv < 0) zv += ZL;
        const float* __restrict__ r = tb + vn * ZL;
        float t0, t1, t2, t3;
        if (zv <= ZL - 4) { t0 = r[zv]; t1 = r[zv + 1]; t2 = r[zv + 2]; t3 = r[zv + 3]; }
        else {
            t0 = r[zv];
            int a1 = zv + 1; if (a1 >= ZL) a1 -= ZL; t1 = r[a1];
            int a2 = zv + 2; if (a2 >= ZL) a2 -= ZL; t2 = r[a2];
            int a3 = zv + 3; if (a3 >= ZL) a3 -= ZL; t3 = r[a3];
        }
        float c0 = 0.f, c1 = 0.f, c2 = 0.f, c3 = 0.f;
        if (!first) {
            const int ec = *(const int*)(eq + e * ZL + z4);   // aligned char4
            c0 = 0.5f * (float)((signed char)(ec));
            c1 = 0.5f * (float)((signed char)(ec >> 8));
            c2 = 0.5f * (float)((signed char)(ec >> 16));
            c3 = 0.5f * (float)((signed char)(ec >> 24));
        }
        float4 vv;
        vv.x = fminf(fmaxf(t0 - c0, -20.f), 20.f);
        vv.y = fminf(fmaxf(t1 - c1, -20.f), 20.f);
        vv.z = fminf(fmaxf(t2 - c2, -20.f), 20.f);
        vv.w = fminf(fmaxf(t3 - c3, -20.f), 20.f);
        v[j] = vv;
        if (vv.x < 0.f) negw |= 1u << (0 * 8 + j);
        if (vv.y < 0.f) negw |= 1u << (1 * 8 + j);
        if (vv.z < 0.f) negw |= 1u << (2 * 8 + j);
        if (vv.w < 0.f) negw |= 1u << (3 * 8 + j);
        m1.x = fminf(m1.x, fabsf(vv.x));
        m1.y = fminf(m1.y, fabsf(vv.y));
        m1.z = fminf(m1.z, fabsf(vv.z));
        m1.w = fminf(m1.w, fabsf(vv.w));
    }
    float4 m2 = make_float4(1e9f, 1e9f, 1e9f, 1e9f);   // BIG
#pragma unroll
    for (int j = 0; j < 8; ++j) {
        float a;
        a = fabsf(v[j].x); if (a != m1.x) m2.x = fminf(m2.x, a);
        a = fabsf(v[j].y); if (a != m1.y) m2.y = fminf(m2.y, a);
        a = fabsf(v[j].z); if (a != m1.z) m2.z = fminf(m2.z, a);
        a = fabsf(v[j].w); if (a != m1.w) m2.w = fminf(m2.w, a);
    }
    const float cs0 = (__popc(negw & 0x000000ffu) & 1) ? -w : w;
    const float cs1 = (__popc(negw & 0x0000ff00u) & 1) ? -w : w;
    const float cs2 = (__popc(negw & 0x00ff0000u) & 1) ? -w : w;
    const float cs3 = (__popc(negw & 0xff000000u) & 1) ? -w : w;
#pragma unroll
    for (int j = 0; j < 8; ++j) {
        const int e = scpack[p0 + j] & 511;
        const int b0 = qbyte(v[j].x, m1.x, m2.x, cs0);
        const int b1 = qbyte(v[j].y, m1.y, m2.y, cs1);
        const int b2 = qbyte(v[j].z, m1.z, m2.z, cs2);
        const int b3 = qbyte(v[j].w, m1.w, m2.w, cs3);
        *(int*)(eq + e * ZL + z4) =
            (b0 & 0xff) | ((b1 & 0xff) << 8) | ((b2 & 0xff) << 16) | (b3 << 24);
    }
}

// ---------------------------------------------------------------------------
extern "C" void kernel_launch(void* const* d_in, const int* in_sizes, int n_in,
                              void* d_out, int out_size) {
    const float* xa  = (const float*)d_in[0];   // [B, N, Z] f32
    const float* cnw = (const float*)d_in[1];   // [ITERS] f32
    const int* evn   = (const int*)d_in[2];     // [E] i32
    const int* ecn   = (const int*)d_in[3];     // [E] i32
    const int* esh   = (const int*)d_in[4];     // [E] i32
    float* out = (float*)d_out;                 // [ITERS, B, Z, N] f32

    k_setup<<<1, 384>>>(evn, ecn, esh);

    dim3 blkV(32, 16);
    dim3 gV(3, BB);                 // 3 quad-tiles of 32 quads (128 z) x batch
    dim3 blkC(32, 8);
    dim3 gC(3, BB, 6);              // quad-tiles x batch x c-groups of 8

    // Iteration 0 VN pass: tot = channel only (state unused)
    k_vn<<<gV, blkV>>>(xa, nullptr, 0, 0, 1);
    for (int it = 0; it < ITERS; ++it) {
        k_cn<<<gC, blkC>>>(cnw, it, it == 0);
        // VN pass of iteration it+1 writes out[it] (== marginalized output of it);
        // the last one needs no tot for a subsequent CN pass.
        k_vn<<<gV, blkV>>>(xa, out + (size_t)it * BB * ZL * NV, 1, 1,
                           it != ITERS - 1);
    }
}

// round 6
// speedup vs baseline: 4.3122x; 1.0657x over previous
#include <cuda_runtime.h>

// Problem constants (fixed by this dataset instance)
#define ITERS 5
#define NV 68      // base VNs
#define MC 46      // base CNs
#define ZL 384     // lifting size
#define NE 368     // edges
#define BB 64      // batch
#define ZW (ZL/4)  // 96 words per edge row

// Persistent scratch (no allocations allowed)
__device__ __align__(16) signed char g_extq[BB * NE * ZL]; // quantized C2V, value = 2*q in [-15,15]
__device__ __align__(16) float       g_tot [BB * NV * ZL]; // total beliefs, layout [b][n][z]
__device__ int g_cnptr[MC + 1];
__device__ int g_cpack[NE];   // CN-order: e | vn<<9 | shift<<16
__device__ int g_vnptr[NV + 1];
__device__ int g_vpack[NE];   // VN-order: e | shift<<16

// ---------------------------------------------------------------------------
// Setup: build CN-CSR and VN-CSR from edge lists (deterministic placement).
// ---------------------------------------------------------------------------
__global__ void k_setup(const int* __restrict__ evn, const int* __restrict__ ecn,
                        const int* __restrict__ esh) {
    __shared__ int s_vn[NE], s_cn[NE], s_sh[NE];
    __shared__ int ccnt[MC], vcnt[NV];
    __shared__ int cbase[MC], vbase[NV];
    int t = threadIdx.x;
    if (t < NE) { s_vn[t] = evn[t]; s_cn[t] = ecn[t]; s_sh[t] = esh[t]; }
    if (t < MC) ccnt[t] = 0;
    if (t < NV) vcnt[t] = 0;
    __syncthreads();
    if (t < NE) { atomicAdd(&ccnt[s_cn[t]], 1); atomicAdd(&vcnt[s_vn[t]], 1); }
    __syncthreads();
    if (t == 0) {
        int run = 0;
        for (int c = 0; c < MC; ++c) { cbase[c] = run; g_cnptr[c] = run; run += ccnt[c]; }
        g_cnptr[MC] = run;
        run = 0;
        for (int n = 0; n < NV; ++n) { vbase[n] = run; g_vnptr[n] = run; run += vcnt[n]; }
        g_vnptr[NV] = run;
    }
    __syncthreads();
    if (t < NE) {
        int c = s_cn[t], v = s_vn[t];
        int pc = 0, pv = 0;
        for (int e2 = 0; e2 < t; ++e2) {     // stable (e-ascending) position
            pc += (s_cn[e2] == c);
            pv += (s_vn[e2] == v);
        }
        g_cpack[cbase[c] + pc] = t | (v << 9) | (s_sh[t] << 16);
        g_vpack[vbase[v] + pv] = t | (s_sh[t] << 16);
    }
}

// ---------------------------------------------------------------------------
// VN update, z-quad per thread. Per edge: 2 aligned word loads + funnelshift,
// then (signed char) extraction into int accumulators (exact).
// Block = (16 quads = 64 z, 32 n-groups) -> grid (6, BB) = 384 blocks for
// occupancy. Writes tot (float4) and optionally the transposed output tile
// out[it-1][b][z][n] via shared.
// ---------------------------------------------------------------------------
__global__ __launch_bounds__(512) void k_vn(const float* __restrict__ xa,
                                            float* __restrict__ out_prev,
                                            int use_state, int write_out,
                                            int write_tot) {
    __shared__ __align__(16) float s[NV][68];    // 16 quads * 4 z + pad (272B rows)
    __shared__ int svptr[NV + 1];
    __shared__ int svpack[NE];
    const int tx = threadIdx.x;           // quad within tile (16)
    const int ty = threadIdx.y;           // n-group (32)
    const int tid = ty * 16 + tx;
    const int b = blockIdx.y;
    const int q0 = blockIdx.x * 16;       // quad tile base
    const int q = q0 + tx;
    const int z4 = q * 4;

    for (int i = tid; i <= NV; i += 512) svptr[i] = g_vnptr[i];
    for (int i = tid; i < NE; i += 512) svpack[i] = g_vpack[i];
    __syncthreads();

    const signed char* __restrict__ eq = g_extq + (size_t)b * (NE * ZL);
    float* __restrict__ tb = g_tot + (size_t)b * (NV * ZL);

    for (int n = ty; n < NV; n += 32) {
        float4 ch = ((const float4*)xa)[((size_t)b * NV + n) * ZW + q];
        if (use_state) {
            int a0 = 0, a1 = 0, a2 = 0, a3 = 0;   // exact integer sums
            const int j1 = svptr[n + 1];
            for (int j = svptr[n]; j < j1; ++j) {
                const int pk = svpack[j];
                const int e = pk & 511;
                int zc = z4 + (pk >> 16); if (zc >= ZL) zc -= ZL;
                const unsigned* __restrict__ row = (const unsigned*)(eq + e * ZL);
                const int w0 = zc >> 2;
                int w1 = w0 + 1; if (w1 == ZW) w1 = 0;
                const unsigned u = __funnelshift_r(row[w0], row[w1], (zc & 3) * 8);
                a0 += (int)(signed char)(u);
                a1 += (int)(signed char)(u >> 8);
                a2 += (int)(signed char)(u >> 16);
                a3 += (int)(signed char)(u >> 24);
            }
            ch.x += 0.5f * (float)a0;
            ch.y += 0.5f * (float)a1;
            ch.z += 0.5f * (float)a2;
            ch.w += 0.5f * (float)a3;
        }
        if (write_tot) ((float4*)tb)[n * ZW + q] = ch;
        *(float4*)&s[n][tx * 4] = ch;
    }
    if (write_out) {
        __syncthreads();
        float4* __restrict__ dst = (float4*)(out_prev + ((size_t)b * ZL + q0 * 4) * NV);
        // 64 z-rows x 17 float4 per row (NV=68)
        for (int f = tid; f < 64 * 17; f += 512) {
            const int zl = f / 17;
            const int n0 = (f - zl * 17) * 4;
            float4 o;
            o.x = s[n0 + 0][zl]; o.y = s[n0 + 1][zl];
            o.z = s[n0 + 2][zl]; o.w = s[n0 + 3][zl];
            dst[f] = o;
        }
    }
}

// ---------------------------------------------------------------------------
// CN update (min-sum, reference-exact tie semantics) + QMS quantize.
// One thread per (b, c, z-quad). Aligned char4 state load/store.
// ---------------------------------------------------------------------------
__device__ __forceinline__ int qbyte(float vv, float mn1, float mn2, float csw) {
    const float em = (fabsf(vv) == mn1) ? mn2 : mn1;
    const float x = (vv < 0.f ? -csw : csw) * em;   // csw = +-w folded; sign flips exact
    float r = rintf(x + x);                          // round-half-even, matches jnp.round
    r = fminf(fmaxf(r, -15.f), 15.f);                // == clip(round(2x)/2,+-7.5) doubled
    return (int)r;
}

__global__ __launch_bounds__(256) void k_cn(const float* __restrict__ cnw,
                                            int it, int first) {
    __shared__ int scptr[MC + 1];
    __shared__ int scpack[NE];
    const int tx = threadIdx.x;           // quad (32)
    const int ty = threadIdx.y;           // c within group (8)
    const int tid = ty * 32 + tx;
    for (int i = tid; i <= MC; i += 256) scptr[i] = g_cnptr[i];
    for (int i = tid; i < NE; i += 256) scpack[i] = g_cpack[i];
    __syncthreads();

    const int b = blockIdx.y;
    const int z4 = (blockIdx.x * 32 + tx) * 4;
    const int c = blockIdx.z * 8 + ty;
    if (c >= MC) return;
    const float w = __ldg(&cnw[it]);
    const float* __restrict__ tb = g_tot + (size_t)b * (NV * ZL);
    signed char* __restrict__ eq = g_extq + (size_t)b * (NE * ZL);

    const int p0 = scptr[c];
    float4 v[8];
    unsigned negw = 0;                    // bit (k*8 + j): sign of edge j at z4+k
    float4 m1 = make_float4(1e30f, 1e30f, 1e30f, 1e30f);
#pragma unroll
    for (int j = 0; j < 8; ++j) {
        const int pk = scpack[p0 + j];
        const int e = pk & 511;
        const int vn = (pk >> 9) & 127;
        int zv = z4 - (pk >> 16); if (zv < 0) zv += ZL;
        const float* __restrict__ r = tb + vn * ZL;
        float t0, t1, t2, t3;
        if (zv <= ZL - 4) { t0 = r[zv]; t1 = r[zv + 1]; t2 = r[zv + 2]; t3 = r[zv + 3]; }
        else {
            t0 = r[zv];
            int a1 = zv + 1; if (a1 >= ZL) a1 -= ZL; t1 = r[a1];
            int a2 = zv + 2; if (a2 >= ZL) a2 -= ZL; t2 = r[a2];
            int a3 = zv + 3; if (a3 >= ZL) a3 -= ZL; t3 = r[a3];
        }
        float c0 = 0.f, c1 = 0.f, c2 = 0.f, c3 = 0.f;
        if (!first) {
            const int ec = *(const int*)(eq + e * ZL + z4);   // aligned char4
            c0 = 0.5f * (float)((signed char)(ec));
            c1 = 0.5f * (float)((signed char)(ec >> 8));
            c2 = 0.5f * (float)((signed char)(ec >> 16));
            c3 = 0.5f * (float)((signed char)(ec >> 24));
        }
        float4 vv;
        vv.x = fminf(fmaxf(t0 - c0, -20.f), 20.f);
        vv.y = fminf(fmaxf(t1 - c1, -20.f), 20.f);
        vv.z = fminf(fmaxf(t2 - c2, -20.f), 20.f);
        vv.w = fminf(fmaxf(t3 - c3, -20.f), 20.f);
        v[j] = vv;
        if (vv.x < 0.f) negw |= 1u << (0 * 8 + j);
        if (vv.y < 0.f) negw |= 1u << (1 * 8 + j);
        if (vv.z < 0.f) negw |= 1u << (2 * 8 + j);
        if (vv.w < 0.f) negw |= 1u << (3 * 8 + j);
        m1.x = fminf(m1.x, fabsf(vv.x));
        m1.y = fminf(m1.y, fabsf(vv.y));
        m1.z = fminf(m1.z, fabsf(vv.z));
        m1.w = fminf(m1.w, fabsf(vv.w));
    }
    float4 m2 = make_float4(1e9f, 1e9f, 1e9f, 1e9f);   // BIG
#pragma unroll
    for (int j = 0; j < 8; ++j) {
        float a;
        a = fabsf(v[j].x); if (a != m1.x) m2.x = fminf(m2.x, a);
        a = fabsf(v[j].y); if (a != m1.y) m2.y = fminf(m2.y, a);
        a = fabsf(v[j].z); if (a != m1.z) m2.z = fminf(m2.z, a);
        a = fabsf(v[j].w); if (a != m1.w) m2.w = fminf(m2.w, a);
    }
    const float cs0 = (__popc(negw & 0x000000ffu) & 1) ? -w : w;
    const float cs1 = (__popc(negw & 0x0000ff00u) & 1) ? -w : w;
    const float cs2 = (__popc(negw & 0x00ff0000u) & 1) ? -w : w;
    const float cs3 = (__popc(negw & 0xff000000u) & 1) ? -w : w;
#pragma unroll
    for (int j = 0; j < 8; ++j) {
        const int e = scpack[p0 + j] & 511;
        const int b0 = qbyte(v[j].x, m1.x, m2.x, cs0);
        const int b1 = qbyte(v[j].y, m1.y, m2.y, cs1);
        const int b2 = qbyte(v[j].z, m1.z, m2.z, cs2);
        const int b3 = qbyte(v[j].w, m1.w, m2.w, cs3);
        *(int*)(eq + e * ZL + z4) =
            (b0 & 0xff) | ((b1 & 0xff) << 8) | ((b2 & 0xff) << 16) | (b3 << 24);
    }
}

// ---------------------------------------------------------------------------
extern "C" void kernel_launch(void* const* d_in, const int* in_sizes, int n_in,
                              void* d_out, int out_size) {
    const float* xa  = (const float*)d_in[0];   // [B, N, Z] f32
    const float* cnw = (const float*)d_in[1];   // [ITERS] f32
    const int* evn   = (const int*)d_in[2];     // [E] i32
    const int* ecn   = (const int*)d_in[3];     // [E] i32
    const int* esh   = (const int*)d_in[4];     // [E] i32
    float* out = (float*)d_out;                 // [ITERS, B, Z, N] f32

    k_setup<<<1, 384>>>(evn, ecn, esh);

    dim3 blkV(16, 32);
    dim3 gV(6, BB);                 // 6 quad-tiles of 16 quads (64 z) x batch
    dim3 blkC(32, 8);
    dim3 gC(3, BB, 6);              // quad-tiles x batch x c-groups of 8

    // Iteration 0 VN pass: tot = channel only (state unused)
    k_vn<<<gV, blkV>>>(xa, nullptr, 0, 0, 1);
    for (int it = 0; it < ITERS; ++it) {
        k_cn<<<gC, blkC>>>(cnw, it, it == 0);
        // VN pass of iteration it+1 writes out[it] (== marginalized output of it);
        // the last one needs no tot for a subsequent CN pass.
        k_vn<<<gV, blkV>>>(xa, out + (size_t)it * BB * ZL * NV, 1, 1,
                           it != ITERS - 1);
    }
}

// round 7
// speedup vs baseline: 4.4271x; 1.0267x over previous
#include <cuda_runtime.h>

// Problem constants (fixed by this dataset instance)
#define ITERS 5
#define NV 68      // base VNs
#define MC 46      // base CNs
#define ZL 384     // lifting size
#define NE 368     // edges
#define BB 64      // batch
#define ZW (ZL/4)  // 96 words per edge row

// Persistent scratch (no allocations allowed)
__device__ __align__(16) signed char g_extq[BB * NE * ZL]; // quantized C2V, value = 2*q in [-15,15]
__device__ __align__(16) float       g_tot [BB * NV * ZL]; // total beliefs, layout [b][n][z]
__device__ int g_cnptr[MC + 1];
__device__ int g_cpack[NE];   // CN-order: e | vn<<9 | shift<<16
__device__ int g_vnptr[NV + 1];
__device__ int g_vpack[NE];   // VN-order: e | shift<<16

// ---------------------------------------------------------------------------
// Setup: build CN-CSR and VN-CSR from edge lists (deterministic placement).
// ---------------------------------------------------------------------------
__global__ void k_setup(const int* __restrict__ evn, const int* __restrict__ ecn,
                        const int* __restrict__ esh) {
    __shared__ int s_vn[NE], s_cn[NE], s_sh[NE];
    __shared__ int ccnt[MC], vcnt[NV];
    __shared__ int cbase[MC], vbase[NV];
    int t = threadIdx.x;
    if (t < NE) { s_vn[t] = evn[t]; s_cn[t] = ecn[t]; s_sh[t] = esh[t]; }
    if (t < MC) ccnt[t] = 0;
    if (t < NV) vcnt[t] = 0;
    __syncthreads();
    if (t < NE) { atomicAdd(&ccnt[s_cn[t]], 1); atomicAdd(&vcnt[s_vn[t]], 1); }
    __syncthreads();
    if (t == 0) {
        int run = 0;
        for (int c = 0; c < MC; ++c) { cbase[c] = run; g_cnptr[c] = run; run += ccnt[c]; }
        g_cnptr[MC] = run;
        run = 0;
        for (int n = 0; n < NV; ++n) { vbase[n] = run; g_vnptr[n] = run; run += vcnt[n]; }
        g_vnptr[NV] = run;
    }
    __syncthreads();
    if (t < NE) {
        int c = s_cn[t], v = s_vn[t];
        int pc = 0, pv = 0;
        for (int e2 = 0; e2 < t; ++e2) {     // stable (e-ascending) position
            pc += (s_cn[e2] == c);
            pv += (s_vn[e2] == v);
        }
        g_cpack[cbase[c] + pc] = t | (v << 9) | (s_sh[t] << 16);
        g_vpack[vbase[v] + pv] = t | (s_sh[t] << 16);
    }
}

// ---------------------------------------------------------------------------
// VN update, z-quad per thread. Edge loop processed in chunks of 4 with
// split issue/consume passes -> 8 loads in flight (MLP 8). Integer
// accumulation is exact (messages are 2*q in [-15,15]).
// Block = (16 quads = 64 z, 32 n-groups), grid (6, BB) = 384 blocks.
// Writes tot (float4) and optionally out[it-1][b][z][n] via shared transpose.
// ---------------------------------------------------------------------------
__global__ __launch_bounds__(512, 2) void k_vn(const float* __restrict__ xa,
                                               float* __restrict__ out_prev,
                                               int write_out, int write_tot) {
    __shared__ __align__(16) float s[NV][68];    // padded transpose rows
    __shared__ int svptr[NV + 1];
    __shared__ int svpack[NE];
    const int tx = threadIdx.x;           // quad within tile (16)
    const int ty = threadIdx.y;           // n-group (32)
    const int tid = ty * 16 + tx;
    const int b = blockIdx.y;
    const int q0 = blockIdx.x * 16;       // quad tile base
    const int q = q0 + tx;
    const int z4 = q * 4;

    for (int i = tid; i <= NV; i += 512) svptr[i] = g_vnptr[i];
    for (int i = tid; i < NE; i += 512) svpack[i] = g_vpack[i];
    __syncthreads();

    const signed char* __restrict__ eq = g_extq + (size_t)b * (NE * ZL);
    float* __restrict__ tb = g_tot + (size_t)b * (NV * ZL);

    for (int n = ty; n < NV; n += 32) {
        float4 ch = ((const float4*)xa)[((size_t)b * NV + n) * ZW + q];
        int a0 = 0, a1 = 0, a2 = 0, a3 = 0;   // exact integer sums
        int j = svptr[n];
        const int j1 = svptr[n + 1];
        while (j < j1) {
            const int cnt = j1 - j;            // >=1
            unsigned ua[4], ub[4];
            int sh[4];
            // Pass A: issue up to 8 independent loads
#pragma unroll
            for (int k = 0; k < 4; ++k) {
                if (k < cnt) {
                    const int pk = svpack[j + k];
                    int zc = z4 + (pk >> 16); if (zc >= ZL) zc -= ZL;
                    const unsigned* __restrict__ row =
                        (const unsigned*)(eq + (pk & 511) * ZL);
                    const int w0 = zc >> 2;
                    int w1 = w0 + 1; if (w1 == ZW) w1 = 0;
                    ua[k] = row[w0];
                    ub[k] = row[w1];
                    sh[k] = (zc & 3) * 8;
                }
            }
            // Pass B: consume
#pragma unroll
            for (int k = 0; k < 4; ++k) {
                if (k < cnt) {
                    const unsigned u = __funnelshift_r(ua[k], ub[k], sh[k]);
                    a0 += (int)(signed char)(u);
                    a1 += (int)(signed char)(u >> 8);
                    a2 += (int)(signed char)(u >> 16);
                    a3 += (int)(signed char)(u >> 24);
                }
            }
            j += 4;
        }
        ch.x += 0.5f * (float)a0;
        ch.y += 0.5f * (float)a1;
        ch.z += 0.5f * (float)a2;
        ch.w += 0.5f * (float)a3;
        if (write_tot) ((float4*)tb)[n * ZW + q] = ch;
        *(float4*)&s[n][tx * 4] = ch;
    }
    if (write_out) {
        __syncthreads();
        float4* __restrict__ dst = (float4*)(out_prev + ((size_t)b * ZL + q0 * 4) * NV);
        // 64 z-rows x 17 float4 per row (NV=68)
        for (int f = tid; f < 64 * 17; f += 512) {
            const int zl = f / 17;
            const int n0 = (f - zl * 17) * 4;
            float4 o;
            o.x = s[n0 + 0][zl]; o.y = s[n0 + 1][zl];
            o.z = s[n0 + 2][zl]; o.w = s[n0 + 3][zl];
            dst[f] = o;
        }
    }
}

// ---------------------------------------------------------------------------
// CN update (min-sum, reference-exact tie semantics) + QMS quantize.
// One thread per (b, c, z-quad). Aligned char4 state load/store.
// On it==0, beliefs come straight from xa (tot == xa identically).
// ---------------------------------------------------------------------------
__device__ __forceinline__ int qbyte(float vv, float mn1, float mn2, float csw) {
    const float em = (fabsf(vv) == mn1) ? mn2 : mn1;
    const float x = (vv < 0.f ? -csw : csw) * em;   // csw = +-w folded; sign flips exact
    float r = rintf(x + x);                          // round-half-even, matches jnp.round
    r = fminf(fmaxf(r, -15.f), 15.f);                // == clip(round(2x)/2,+-7.5) doubled
    return (int)r;
}

__global__ __launch_bounds__(256) void k_cn(const float* __restrict__ cnw,
                                            const float* __restrict__ xa,
                                            int it, int first) {
    __shared__ int scptr[MC + 1];
    __shared__ int scpack[NE];
    const int tx = threadIdx.x;           // quad (32)
    const int ty = threadIdx.y;           // c within group (8)
    const int tid = ty * 32 + tx;
    for (int i = tid; i <= MC; i += 256) scptr[i] = g_cnptr[i];
    for (int i = tid; i < NE; i += 256) scpack[i] = g_cpack[i];
    __syncthreads();

    const int b = blockIdx.y;
    const int z4 = (blockIdx.x * 32 + tx) * 4;
    const int c = blockIdx.z * 8 + ty;
    if (c >= MC) return;
    const float w = __ldg(&cnw[it]);
    const float* __restrict__ tb =
        (first ? xa : (const float*)g_tot) + (size_t)b * (NV * ZL);
    signed char* __restrict__ eq = g_extq + (size_t)b * (NE * ZL);

    const int p0 = scptr[c];
    float4 v[8];
    unsigned negw = 0;                    // bit (k*8 + j): sign of edge j at z4+k
    float4 m1 = make_float4(1e30f, 1e30f, 1e30f, 1e30f);
#pragma unroll
    for (int j = 0; j < 8; ++j) {
        const int pk = scpack[p0 + j];
        const int e = pk & 511;
        const int vn = (pk >> 9) & 127;
        int zv = z4 - (pk >> 16); if (zv < 0) zv += ZL;
        const float* __restrict__ r = tb + vn * ZL;
        float t0, t1, t2, t3;
        if (zv <= ZL - 4) { t0 = r[zv]; t1 = r[zv + 1]; t2 = r[zv + 2]; t3 = r[zv + 3]; }
        else {
            t0 = r[zv];
            int a1 = zv + 1; if (a1 >= ZL) a1 -= ZL; t1 = r[a1];
            int a2 = zv + 2; if (a2 >= ZL) a2 -= ZL; t2 = r[a2];
            int a3 = zv + 3; if (a3 >= ZL) a3 -= ZL; t3 = r[a3];
        }
        float c0 = 0.f, c1 = 0.f, c2 = 0.f, c3 = 0.f;
        if (!first) {
            const int ec = *(const int*)(eq + e * ZL + z4);   // aligned char4
            c0 = 0.5f * (float)((signed char)(ec));
            c1 = 0.5f * (float)((signed char)(ec >> 8));
            c2 = 0.5f * (float)((signed char)(ec >> 16));
            c3 = 0.5f * (float)((signed char)(ec >> 24));
        }
        float4 vv;
        vv.x = fminf(fmaxf(t0 - c0, -20.f), 20.f);
        vv.y = fminf(fmaxf(t1 - c1, -20.f), 20.f);
        vv.z = fminf(fmaxf(t2 - c2, -20.f), 20.f);
        vv.w = fminf(fmaxf(t3 - c3, -20.f), 20.f);
        v[j] = vv;
        if (vv.x < 0.f) negw |= 1u << (0 * 8 + j);
        if (vv.y < 0.f) negw |= 1u << (1 * 8 + j);
        if (vv.z < 0.f) negw |= 1u << (2 * 8 + j);
        if (vv.w < 0.f) negw |= 1u << (3 * 8 + j);
        m1.x = fminf(m1.x, fabsf(vv.x));
        m1.y = fminf(m1.y, fabsf(vv.y));
        m1.z = fminf(m1.z, fabsf(vv.z));
        m1.w = fminf(m1.w, fabsf(vv.w));
    }
    float4 m2 = make_float4(1e9f, 1e9f, 1e9f, 1e9f);   // BIG
#pragma unroll
    for (int j = 0; j < 8; ++j) {
        float a;
        a = fabsf(v[j].x); if (a != m1.x) m2.x = fminf(m2.x, a);
        a = fabsf(v[j].y); if (a != m1.y) m2.y = fminf(m2.y, a);
        a = fabsf(v[j].z); if (a != m1.z) m2.z = fminf(m2.z, a);
        a = fabsf(v[j].w); if (a != m1.w) m2.w = fminf(m2.w, a);
    }
    const float cs0 = (__popc(negw & 0x000000ffu) & 1) ? -w : w;
    const float cs1 = (__popc(negw & 0x0000ff00u) & 1) ? -w : w;
    const float cs2 = (__popc(negw & 0x00ff0000u) & 1) ? -w : w;
    const float cs3 = (__popc(negw & 0xff000000u) & 1) ? -w : w;
#pragma unroll
    for (int j = 0; j < 8; ++j) {
        const int e = scpack[p0 + j] & 511;
        const int b0 = qbyte(v[j].x, m1.x, m2.x, cs0);
        const int b1 = qbyte(v[j].y, m1.y, m2.y, cs1);
        const int b2 = qbyte(v[j].z, m1.z, m2.z, cs2);
        const int b3 = qbyte(v[j].w, m1.w, m2.w, cs3);
        *(int*)(eq + e * ZL + z4) =
            (b0 & 0xff) | ((b1 & 0xff) << 8) | ((b2 & 0xff) << 16) | (b3 << 24);
    }
}

// ---------------------------------------------------------------------------
extern "C" void kernel_launch(void* const* d_in, const int* in_sizes, int n_in,
                              void* d_out, int out_size) {
    const float* xa  = (const float*)d_in[0];   // [B, N, Z] f32
    const float* cnw = (const float*)d_in[1];   // [ITERS] f32
    const int* evn   = (const int*)d_in[2];     // [E] i32
    const int* ecn   = (const int*)d_in[3];     // [E] i32
    const int* esh   = (const int*)d_in[4];     // [E] i32
    float* out = (float*)d_out;                 // [ITERS, B, Z, N] f32

    k_setup<<<1, 384>>>(evn, ecn, esh);

    dim3 blkV(16, 32);
    dim3 gV(6, BB);                 // 6 quad-tiles of 16 quads (64 z) x batch
    dim3 blkC(32, 8);
    dim3 gC(3, BB, 6);              // quad-tiles x batch x c-groups of 8

    for (int it = 0; it < ITERS; ++it) {
        // it==0 reads beliefs straight from xa (tot == xa), no priming k_vn.
        k_cn<<<gC, blkC>>>(cnw, xa, it, it == 0);
        // VN pass of iteration it+1 writes out[it] (== marginalized output of
        // it); the last one needs no tot for a subsequent CN pass.
        k_vn<<<gV, blkV>>>(xa, out + (size_t)it * BB * ZL * NV, 1,
                           it != ITERS - 1);
    }
}

// round 8
// speedup vs baseline: 4.6774x; 1.0565x over previous
#include <cuda_runtime.h>

// Problem constants (fixed by this dataset instance)
#define ITERS 5
#define NV 68      // base VNs
#define MC 46      // base CNs
#define ZL 384     // lifting size
#define NE 368     // edges
#define BB 64      // batch
#define ZW (ZL/4)  // 96 words per edge row

// Persistent scratch (no allocations allowed)
__device__ __align__(16) signed char g_extq[BB * NE * ZL]; // quantized C2V, value = 2*q in [-15,15]
__device__ __align__(16) float       g_tot [BB * NV * ZL]; // total beliefs, layout [b][n][z]
__device__ int g_cnptr[MC + 1];
__device__ int g_cpack[NE];   // CN-order: e | vn<<9 | shift<<16
__device__ int g_vnptr[NV + 1];
__device__ int g_vpack[NE];   // VN-order: e | shift<<16

// ---------------------------------------------------------------------------
// Setup: build CN-CSR and VN-CSR from edge lists (deterministic placement).
// ---------------------------------------------------------------------------
__global__ void k_setup(const int* __restrict__ evn, const int* __restrict__ ecn,
                        const int* __restrict__ esh) {
    __shared__ int s_vn[NE], s_cn[NE], s_sh[NE];
    __shared__ int ccnt[MC], vcnt[NV];
    __shared__ int cbase[MC], vbase[NV];
    int t = threadIdx.x;
    if (t < NE) { s_vn[t] = evn[t]; s_cn[t] = ecn[t]; s_sh[t] = esh[t]; }
    if (t < MC) ccnt[t] = 0;
    if (t < NV) vcnt[t] = 0;
    __syncthreads();
    if (t < NE) { atomicAdd(&ccnt[s_cn[t]], 1); atomicAdd(&vcnt[s_vn[t]], 1); }
    __syncthreads();
    if (t == 0) {
        int run = 0;
        for (int c = 0; c < MC; ++c) { cbase[c] = run; g_cnptr[c] = run; run += ccnt[c]; }
        g_cnptr[MC] = run;
        run = 0;
        for (int n = 0; n < NV; ++n) { vbase[n] = run; g_vnptr[n] = run; run += vcnt[n]; }
        g_vnptr[NV] = run;
    }
    __syncthreads();
    if (t < NE) {
        int c = s_cn[t], v = s_vn[t];
        int pc = 0, pv = 0;
        for (int e2 = 0; e2 < t; ++e2) {     // stable (e-ascending) position
            pc += (s_cn[e2] == c);
            pv += (s_vn[e2] == v);
        }
        g_cpack[cbase[c] + pc] = t | (v << 9) | (s_sh[t] << 16);
        g_vpack[vbase[v] + pv] = t | (s_sh[t] << 16);
    }
}

// ---------------------------------------------------------------------------
// VN update, z-quad per thread. Edge loop processed in chunks of 4 with
// split issue/consume passes -> 8 loads in flight (MLP 8). Integer
// accumulation is exact (messages are 2*q in [-15,15]).
// Block = (16 quads = 64 z, 32 n-groups), grid (6, BB) = 384 blocks.
// Writes tot (float4) and optionally out[it-1][b][z][n] via shared transpose.
// ---------------------------------------------------------------------------
__global__ __launch_bounds__(512, 2) void k_vn(const float* __restrict__ xa,
                                               float* __restrict__ out_prev,
                                               int write_out, int write_tot) {
    __shared__ __align__(16) float s[NV][68];    // padded transpose rows
    __shared__ int svptr[NV + 1];
    __shared__ int svpack[NE];
    const int tx = threadIdx.x;           // quad within tile (16)
    const int ty = threadIdx.y;           // n-group (32)
    const int tid = ty * 16 + tx;
    const int b = blockIdx.y;
    const int q0 = blockIdx.x * 16;       // quad tile base
    const int q = q0 + tx;
    const int z4 = q * 4;

    for (int i = tid; i <= NV; i += 512) svptr[i] = g_vnptr[i];
    for (int i = tid; i < NE; i += 512) svpack[i] = g_vpack[i];
    __syncthreads();

    const signed char* __restrict__ eq = g_extq + (size_t)b * (NE * ZL);
    float* __restrict__ tb = g_tot + (size_t)b * (NV * ZL);

    for (int n = ty; n < NV; n += 32) {
        float4 ch = ((const float4*)xa)[((size_t)b * NV + n) * ZW + q];
        int a0 = 0, a1 = 0, a2 = 0, a3 = 0;   // exact integer sums
        int j = svptr[n];
        const int j1 = svptr[n + 1];
        while (j < j1) {
            const int cnt = j1 - j;            // >=1
            unsigned ua[4], ub[4];
            int sh[4];
            // Pass A: issue up to 8 independent loads
#pragma unroll
            for (int k = 0; k < 4; ++k) {
                if (k < cnt) {
                    const int pk = svpack[j + k];
                    int zc = z4 + (pk >> 16); if (zc >= ZL) zc -= ZL;
                    const unsigned* __restrict__ row =
                        (const unsigned*)(eq + (pk & 511) * ZL);
                    const int w0 = zc >> 2;
                    int w1 = w0 + 1; if (w1 == ZW) w1 = 0;
                    ua[k] = row[w0];
                    ub[k] = row[w1];
                    sh[k] = (zc & 3) * 8;
                }
            }
            // Pass B: consume
#pragma unroll
            for (int k = 0; k < 4; ++k) {
                if (k < cnt) {
                    const unsigned u = __funnelshift_r(ua[k], ub[k], sh[k]);
                    a0 += (int)(signed char)(u);
                    a1 += (int)(signed char)(u >> 8);
                    a2 += (int)(signed char)(u >> 16);
                    a3 += (int)(signed char)(u >> 24);
                }
            }
            j += 4;
        }
        ch.x += 0.5f * (float)a0;
        ch.y += 0.5f * (float)a1;
        ch.z += 0.5f * (float)a2;
        ch.w += 0.5f * (float)a3;
        if (write_tot) ((float4*)tb)[n * ZW + q] = ch;
        *(float4*)&s[n][tx * 4] = ch;
    }
    if (write_out) {
        __syncthreads();
        float4* __restrict__ dst = (float4*)(out_prev + ((size_t)b * ZL + q0 * 4) * NV);
        // 64 z-rows x 17 float4 per row (NV=68)
        for (int f = tid; f < 64 * 17; f += 512) {
            const int zl = f / 17;
            const int n0 = (f - zl * 17) * 4;
            float4 o;
            o.x = s[n0 + 0][zl]; o.y = s[n0 + 1][zl];
            o.z = s[n0 + 2][zl]; o.w = s[n0 + 3][zl];
            dst[f] = o;
        }
    }
}

// ---------------------------------------------------------------------------
// CN update (min-sum, reference-exact tie semantics) + QMS quantize.
// One thread per (b, c, z-pair). Pass-A batched loads (MLP ~24), aligned
// short state load/store. On it==0, beliefs come straight from xa.
// ---------------------------------------------------------------------------
__device__ __forceinline__ int qbyte(float vv, float mn1, float mn2, float csw) {
    const float em = (fabsf(vv) == mn1) ? mn2 : mn1;
    const float x = (vv < 0.f ? -csw : csw) * em;   // csw = +-w folded; sign flips exact
    float r = rintf(x + x);                          // round-half-even, matches jnp.round
    r = fminf(fmaxf(r, -15.f), 15.f);                // == clip(round(2x)/2,+-7.5) doubled
    return (int)r;
}

__global__ __launch_bounds__(256, 4) void k_cn(const float* __restrict__ cnw,
                                               const float* __restrict__ xa,
                                               int it, int first) {
    __shared__ int scptr[MC + 1];
    __shared__ int scpack[NE];
    const int tx = threadIdx.x;           // z-pair (64)
    const int ty = threadIdx.y;           // c within group (4)
    const int tid = ty * 64 + tx;
    for (int i = tid; i <= MC; i += 256) scptr[i] = g_cnptr[i];
    for (int i = tid; i < NE; i += 256) scpack[i] = g_cpack[i];
    __syncthreads();

    const int b = blockIdx.y;
    const int z2 = (blockIdx.x * 64 + tx) * 2;
    const int c = blockIdx.z * 4 + ty;
    if (c >= MC) return;
    const float w = __ldg(&cnw[it]);
    const float* __restrict__ tb =
        (first ? xa : (const float*)g_tot) + (size_t)b * (NV * ZL);
    signed char* __restrict__ eq = g_extq + (size_t)b * (NE * ZL);

    const int p0 = scptr[c];
    // Pass A: batch all loads (16 tot floats + 8 state shorts in flight)
    float t0[8], t1[8];
    int es[8];
#pragma unroll
    for (int j = 0; j < 8; ++j) {
        const int pk = scpack[p0 + j];
        const int vn = (pk >> 9) & 127;
        int zv = z2 - (pk >> 16); if (zv < 0) zv += ZL;
        const float* __restrict__ r = tb + vn * ZL;
        t0[j] = r[zv];
        int zn = zv + 1; if (zn == ZL) zn = 0;
        t1[j] = r[zn];
        es[j] = first ? 0 : (int)*(const short*)(eq + (pk & 511) * ZL + z2);
    }
    // Pass B: extrinsic beliefs, signs, min1
    float2 v[8];
    unsigned negw = 0;                    // bits 0-7: z lane 0, bits 8-15: z lane 1
    float mn1x = 1e30f, mn1y = 1e30f;
#pragma unroll
    for (int j = 0; j < 8; ++j) {
        const float c0 = 0.5f * (float)((signed char)(es[j]));
        const float c1 = 0.5f * (float)((signed char)(es[j] >> 8));
        const float vx = fminf(fmaxf(t0[j] - c0, -20.f), 20.f);
        const float vy = fminf(fmaxf(t1[j] - c1, -20.f), 20.f);
        v[j].x = vx; v[j].y = vy;
        if (vx < 0.f) negw |= 1u << j;
        if (vy < 0.f) negw |= 1u << (8 + j);
        mn1x = fminf(mn1x, fabsf(vx));
        mn1y = fminf(mn1y, fabsf(vy));
    }
    float mn2x = 1e9f, mn2y = 1e9f;       // BIG, matches reference when all tie
#pragma unroll
    for (int j = 0; j < 8; ++j) {
        float a;
        a = fabsf(v[j].x); if (a != mn1x) mn2x = fminf(mn2x, a);
        a = fabsf(v[j].y); if (a != mn1y) mn2y = fminf(mn2y, a);
    }
    const float cs0 = (__popc(negw & 0x00ffu) & 1) ? -w : w;
    const float cs1 = (__popc(negw & 0xff00u) & 1) ? -w : w;
#pragma unroll
    for (int j = 0; j < 8; ++j) {
        const int e = scpack[p0 + j] & 511;
        const int b0 = qbyte(v[j].x, mn1x, mn2x, cs0);
        const int b1 = qbyte(v[j].y, mn1y, mn2y, cs1);
        *(short*)(eq + e * ZL + z2) = (short)((b0 & 0xff) | (b1 << 8));
    }
}

// ---------------------------------------------------------------------------
extern "C" void kernel_launch(void* const* d_in, const int* in_sizes, int n_in,
                              void* d_out, int out_size) {
    const float* xa  = (const float*)d_in[0];   // [B, N, Z] f32
    const float* cnw = (const float*)d_in[1];   // [ITERS] f32
    const int* evn   = (const int*)d_in[2];     // [E] i32
    const int* ecn   = (const int*)d_in[3];     // [E] i32
    const int* esh   = (const int*)d_in[4];     // [E] i32
    float* out = (float*)d_out;                 // [ITERS, B, Z, N] f32

    k_setup<<<1, 384>>>(evn, ecn, esh);

    dim3 blkV(16, 32);
    dim3 gV(6, BB);                 // 6 quad-tiles of 16 quads (64 z) x batch
    dim3 blkC(64, 4);
    dim3 gC(3, BB, 12);             // pair-tiles (192 pairs) x batch x c-groups of 4

    for (int it = 0; it < ITERS; ++it) {
        // it==0 reads beliefs straight from xa (tot == xa), no priming k_vn.
        k_cn<<<gC, blkC>>>(cnw, xa, it, it == 0);
        // VN pass of iteration it+1 writes out[it] (== marginalized output of
        // it); the last one needs no tot for a subsequent CN pass.
        k_vn<<<gV, blkV>>>(xa, out + (size_t)it * BB * ZL * NV, 1,
                           it != ITERS - 1);
    }
}

// round 9
// speedup vs baseline: 5.0810x; 1.0863x over previous
#include <cuda_runtime.h>

// Problem constants (fixed by this dataset instance)
#define ITERS 5
#define NV 68      // base VNs
#define MC 46      // base CNs
#define ZL 384     // lifting size
#define NE 368     // edges (= MC*8, regular degree-8 checks by construction)
#define BB 64      // batch
#define ZW (ZL/4)  // 96 words per edge row
#define QZ 96      // z-quads per row

// Persistent scratch (no allocations allowed)
__device__ __align__(16) signed char g_extq[BB * NE * ZL]; // quantized C2V, value = 2*q in [-15,15]
__device__ __align__(16) float       g_tot [BB * NV * ZL]; // total beliefs, layout [b][n][z]
__device__ int2 g_cpack2[NE];   // CN-order: {vn*ZL | sh<<18, e*ZL}
__device__ int g_vnptr[NV + 1];
__device__ int g_vpack[NE];     // VN-order: e | shift<<16

// ---------------------------------------------------------------------------
// Setup: build CN-ordered packed metadata and VN-CSR (deterministic).
// ---------------------------------------------------------------------------
__global__ void k_setup(const int* __restrict__ evn, const int* __restrict__ ecn,
                        const int* __restrict__ esh) {
    __shared__ int s_vn[NE], s_cn[NE], s_sh[NE];
    __shared__ int ccnt[MC], vcnt[NV];
    __shared__ int cbase[MC], vbase[NV];
    int t = threadIdx.x;
    if (t < NE) { s_vn[t] = evn[t]; s_cn[t] = ecn[t]; s_sh[t] = esh[t]; }
    if (t < MC) ccnt[t] = 0;
    if (t < NV) vcnt[t] = 0;
    __syncthreads();
    if (t < NE) { atomicAdd(&ccnt[s_cn[t]], 1); atomicAdd(&vcnt[s_vn[t]], 1); }
    __syncthreads();
    if (t == 0) {
        int run = 0;
        for (int c = 0; c < MC; ++c) { cbase[c] = run; run += ccnt[c]; }
        run = 0;
        for (int n = 0; n < NV; ++n) { vbase[n] = run; g_vnptr[n] = run; run += vcnt[n]; }
        g_vnptr[NV] = run;
    }
    __syncthreads();
    if (t < NE) {
        int c = s_cn[t], v = s_vn[t];
        int pc = 0, pv = 0;
        for (int e2 = 0; e2 < t; ++e2) {     // stable (e-ascending) position
            pc += (s_cn[e2] == c);
            pv += (s_vn[e2] == v);
        }
        g_cpack2[cbase[c] + pc] = make_int2((v * ZL) | (s_sh[t] << 18), t * ZL);
        g_vpack[vbase[v] + pv] = t | (s_sh[t] << 16);
    }
}

// ---------------------------------------------------------------------------
// VN update, z-quad per thread. Edge loop processed in chunks of 4 with
// split issue/consume passes -> 8 loads in flight. Integer accumulation is
// exact (messages are 2*q in [-15,15]).
// ---------------------------------------------------------------------------
__global__ __launch_bounds__(512, 2) void k_vn(const float* __restrict__ xa,
                                               float* __restrict__ out_prev,
                                               int write_out, int write_tot) {
    __shared__ __align__(16) float s[NV][68];    // padded transpose rows
    __shared__ int svptr[NV + 1];
    __shared__ int svpack[NE];
    const int tx = threadIdx.x;           // quad within tile (16)
    const int ty = threadIdx.y;           // n-group (32)
    const int tid = ty * 16 + tx;
    const int b = blockIdx.y;
    const int q0 = blockIdx.x * 16;       // quad tile base
    const int q = q0 + tx;
    const int z4 = q * 4;

    for (int i = tid; i <= NV; i += 512) svptr[i] = g_vnptr[i];
    for (int i = tid; i < NE; i += 512) svpack[i] = g_vpack[i];
    __syncthreads();

    const signed char* __restrict__ eq = g_extq + (size_t)b * (NE * ZL);
    float* __restrict__ tb = g_tot + (size_t)b * (NV * ZL);

    for (int n = ty; n < NV; n += 32) {
        float4 ch = ((const float4*)xa)[((size_t)b * NV + n) * ZW + q];
        int a0 = 0, a1 = 0, a2 = 0, a3 = 0;   // exact integer sums
        int j = svptr[n];
        const int j1 = svptr[n + 1];
        while (j < j1) {
            const int cnt = j1 - j;            // >=1
            unsigned ua[4], ub[4];
            int sh[4];
#pragma unroll
            for (int k = 0; k < 4; ++k) {
                if (k < cnt) {
                    const int pk = svpack[j + k];
                    int zc = z4 + (pk >> 16); if (zc >= ZL) zc -= ZL;
                    const unsigned* __restrict__ row =
                        (const unsigned*)(eq + (pk & 511) * ZL);
                    const int w0 = zc >> 2;
                    int w1 = w0 + 1; if (w1 == ZW) w1 = 0;
                    ua[k] = row[w0];
                    ub[k] = row[w1];
                    sh[k] = (zc & 3) * 8;
                }
            }
#pragma unroll
            for (int k = 0; k < 4; ++k) {
                if (k < cnt) {
                    const unsigned u = __funnelshift_r(ua[k], ub[k], sh[k]);
                    a0 += (int)(signed char)(u);
                    a1 += (int)(signed char)(u >> 8);
                    a2 += (int)(signed char)(u >> 16);
                    a3 += (int)(signed char)(u >> 24);
                }
            }
            j += 4;
        }
        ch.x += 0.5f * (float)a0;
        ch.y += 0.5f * (float)a1;
        ch.z += 0.5f * (float)a2;
        ch.w += 0.5f * (float)a3;
        if (write_tot) ((float4*)tb)[n * ZW + q] = ch;
        *(float4*)&s[n][tx * 4] = ch;
    }
    if (write_out) {
        __syncthreads();
        float4* __restrict__ dst = (float4*)(out_prev + ((size_t)b * ZL + q0 * 4) * NV);
        for (int f = tid; f < 64 * 17; f += 512) {
            const int zl = f / 17;
            const int n0 = (f - zl * 17) * 4;
            float4 o;
            o.x = s[n0 + 0][zl]; o.y = s[n0 + 1][zl];
            o.z = s[n0 + 2][zl]; o.w = s[n0 + 3][zl];
            dst[f] = o;
        }
    }
}

// ---------------------------------------------------------------------------
// CN update (min-sum, reference-exact tie semantics) + integer quantizer.
// One thread per (b, c, z-quad); flattened (c,q), 192-thread blocks, no tail.
// ext value in {m1, m2} -> rounded ints precomputed per z; sign = XOR of
// sign bits (no -0 can occur; w sign folded into accumulator init).
// ---------------------------------------------------------------------------
__global__ __launch_bounds__(192, 5) void k_cn(const float* __restrict__ cnw,
                                               const float* __restrict__ xa,
                                               int it, int first) {
    __shared__ int2 sc[NE];
    const int tid = threadIdx.x;
    for (int i = tid; i < NE; i += 192) sc[i] = g_cpack2[i];
    __syncthreads();

    const int b = blockIdx.y;
    const int idx = blockIdx.x * 192 + tid;   // 0..4415 = (c,q)
    const int c = idx / QZ;
    const int q = idx - c * QZ;
    const int z4 = q * 4;
    const float w = __ldg(&cnw[it]);
    const float w2m = fabsf(w + w);
    const unsigned wsb = __float_as_uint(w) & 0x80000000u;
    const float* __restrict__ tb =
        (first ? xa : (const float*)g_tot) + (size_t)b * (NV * ZL);
    signed char* __restrict__ eqz = g_extq + (size_t)b * (NE * ZL) + z4;

    float v0[8], v1[8], v2[8], v3[8];
    unsigned s0 = wsb, s1 = wsb, s2 = wsb, s3 = wsb;  // running sign XOR (+w sign)
    float m10 = 1e30f, m11 = 1e30f, m12 = 1e30f, m13 = 1e30f;
#pragma unroll
    for (int j = 0; j < 8; ++j) {
        const int2 pk = sc[c * 8 + j];
        const int vnoff = pk.x & 0x3FFFF;
        const int sh = pk.x >> 18;
        int zv = z4 - sh; if (zv < 0) zv += ZL;
        const float* __restrict__ r = tb + vnoff;
        float t0, t1, t2, t3;
        if (zv <= ZL - 4) { t0 = r[zv]; t1 = r[zv + 1]; t2 = r[zv + 2]; t3 = r[zv + 3]; }
        else {
            t0 = r[zv];
            int a = zv + 1; if (a >= ZL) a -= ZL; t1 = r[a];
            a = zv + 2; if (a >= ZL) a -= ZL; t2 = r[a];
            a = zv + 3; if (a >= ZL) a -= ZL; t3 = r[a];
        }
        int es = 0;
        if (!first) es = *(const int*)(eqz + pk.y);      // aligned char4
        const float c0 = 0.5f * (float)((signed char)(es));
        const float c1 = 0.5f * (float)((signed char)(es >> 8));
        const float c2 = 0.5f * (float)((signed char)(es >> 16));
        const float c3 = 0.5f * (float)((signed char)(es >> 24));
        const float a0 = fminf(fmaxf(t0 - c0, -20.f), 20.f);
        const float a1 = fminf(fmaxf(t1 - c1, -20.f), 20.f);
        const float a2 = fminf(fmaxf(t2 - c2, -20.f), 20.f);
        const float a3 = fminf(fmaxf(t3 - c3, -20.f), 20.f);
        v0[j] = a0; v1[j] = a1; v2[j] = a2; v3[j] = a3;
        s0 ^= __float_as_uint(a0); s1 ^= __float_as_uint(a1);
        s2 ^= __float_as_uint(a2); s3 ^= __float_as_uint(a3);
        m10 = fminf(m10, fabsf(a0)); m11 = fminf(m11, fabsf(a1));
        m12 = fminf(m12, fabsf(a2)); m13 = fminf(m13, fabsf(a3));
    }
    float m20 = 1e9f, m21 = 1e9f, m22 = 1e9f, m23 = 1e9f;  // BIG
#pragma unroll
    for (int j = 0; j < 8; ++j) {
        float a;
        a = fabsf(v0[j]); if (a != m10) m20 = fminf(m20, a);
        a = fabsf(v1[j]); if (a != m11) m21 = fminf(m21, a);
        a = fabsf(v2[j]); if (a != m12) m22 = fminf(m22, a);
        a = fabsf(v3[j]); if (a != m13) m23 = fminf(m23, a);
    }
    // Precomputed quantized magnitudes (value stored = 2*q in [-15,15]):
    // round-half-even via __float2int_rn; clip-then-round == round-then-clip at 15.
    const int i10 = __float2int_rn(fminf(w2m * m10, 15.f));
    const int i20 = __float2int_rn(fminf(w2m * m20, 15.f));
    const int i11 = __float2int_rn(fminf(w2m * m11, 15.f));
    const int i21 = __float2int_rn(fminf(w2m * m21, 15.f));
    const int i12 = __float2int_rn(fminf(w2m * m12, 15.f));
    const int i22 = __float2int_rn(fminf(w2m * m22, 15.f));
    const int i13 = __float2int_rn(fminf(w2m * m13, 15.f));
    const int i23 = __float2int_rn(fminf(w2m * m23, 15.f));
#pragma unroll
    for (int j = 0; j < 8; ++j) {
        const int ey = sc[c * 8 + j].y;
        int u, m, sel, b0, b1, b2, b3;
        u = (int)(s0 ^ __float_as_uint(v0[j])); m = u >> 31;
        sel = (fabsf(v0[j]) == m10) ? i20 : i10; b0 = (sel ^ m) - m;
        u = (int)(s1 ^ __float_as_uint(v1[j])); m = u >> 31;
        sel = (fabsf(v1[j]) == m11) ? i21 : i11; b1 = (sel ^ m) - m;
        u = (int)(s2 ^ __float_as_uint(v2[j])); m = u >> 31;
        sel = (fabsf(v2[j]) == m12) ? i22 : i12; b2 = (sel ^ m) - m;
        u = (int)(s3 ^ __float_as_uint(v3[j])); m = u >> 31;
        sel = (fabsf(v3[j]) == m13) ? i23 : i13; b3 = (sel ^ m) - m;
        *(int*)(eqz + ey) =
            (b0 & 0xff) | ((b1 & 0xff) << 8) | ((b2 & 0xff) << 16) | (b3 << 24);
    }
}

// ---------------------------------------------------------------------------
extern "C" void kernel_launch(void* const* d_in, const int* in_sizes, int n_in,
                              void* d_out, int out_size) {
    const float* xa  = (const float*)d_in[0];   // [B, N, Z] f32
    const float* cnw = (const float*)d_in[1];   // [ITERS] f32
    const int* evn   = (const int*)d_in[2];     // [E] i32
    const int* ecn   = (const int*)d_in[3];     // [E] i32
    const int* esh   = (const int*)d_in[4];     // [E] i32
    float* out = (float*)d_out;                 // [ITERS, B, Z, N] f32

    k_setup<<<1, 384>>>(evn, ecn, esh);

    dim3 blkV(16, 32);
    dim3 gV(6, BB);                 // 6 quad-tiles of 16 quads (64 z) x batch
    dim3 gC(23, BB);                // 23 * 192 = 4416 = MC * QZ, no tail

    for (int it = 0; it < ITERS; ++it) {
        // it==0 reads beliefs straight from xa (tot == xa), no priming k_vn.
        k_cn<<<gC, 192>>>(cnw, xa, it, it == 0);
        // VN pass of iteration it+1 writes out[it] (== marginalized output of
        // it); the last one needs no tot for a subsequent CN pass.
        k_vn<<<gV, blkV>>>(xa, out + (size_t)it * BB * ZL * NV, 1,
                           it != ITERS - 1);
    }
}

// round 10
// speedup vs baseline: 5.3267x; 1.0484x over previous
#include <cuda_runtime.h>

// Problem constants (fixed by this dataset instance)
#define ITERS 5
#define NV 68      // base VNs
#define MC 46      // base CNs
#define ZL 384     // lifting size
#define NE 368     // edges (= MC*8, regular degree-8 checks by construction)
#define BB 64      // batch
#define ZW (ZL/4)  // 96 words per edge row

// Persistent scratch (no allocations allowed)
__device__ __align__(16) signed char g_extq[BB * NE * ZL]; // quantized C2V, value = 2*q in [-15,15]
__device__ __align__(16) float       g_tot [BB * NV * ZL]; // total beliefs, layout [b][n][z]
// CN-ordered per-edge metadata (uniform per CN-block in k_cn)
__device__ int g_cvn[NE];   // vn * ZL
__device__ int g_csh[NE];   // shift
__device__ int g_ceo[NE];   // e * ZL
// VN CSR for k_vn
__device__ int g_vnptr[NV + 1];
__device__ int g_vpack[NE];     // VN-order: e | shift<<16

// ---------------------------------------------------------------------------
// Setup: build CN-ordered metadata arrays and VN-CSR (deterministic).
// ---------------------------------------------------------------------------
__global__ void k_setup(const int* __restrict__ evn, const int* __restrict__ ecn,
                        const int* __restrict__ esh) {
    __shared__ int s_vn[NE], s_cn[NE], s_sh[NE];
    __shared__ int ccnt[MC], vcnt[NV];
    __shared__ int cbase[MC], vbase[NV];
    int t = threadIdx.x;
    if (t < NE) { s_vn[t] = evn[t]; s_cn[t] = ecn[t]; s_sh[t] = esh[t]; }
    if (t < MC) ccnt[t] = 0;
    if (t < NV) vcnt[t] = 0;
    __syncthreads();
    if (t < NE) { atomicAdd(&ccnt[s_cn[t]], 1); atomicAdd(&vcnt[s_vn[t]], 1); }
    __syncthreads();
    if (t == 0) {
        int run = 0;
        for (int c = 0; c < MC; ++c) { cbase[c] = run; run += ccnt[c]; }
        run = 0;
        for (int n = 0; n < NV; ++n) { vbase[n] = run; g_vnptr[n] = run; run += vcnt[n]; }
        g_vnptr[NV] = run;
    }
    __syncthreads();
    if (t < NE) {
        int c = s_cn[t], v = s_vn[t];
        int pc = 0, pv = 0;
        for (int e2 = 0; e2 < t; ++e2) {     // stable (e-ascending) position
            pc += (s_cn[e2] == c);
            pv += (s_vn[e2] == v);
        }
        const int pos = cbase[c] + pc;
        g_cvn[pos] = v * ZL;
        g_csh[pos] = s_sh[t];
        g_ceo[pos] = t * ZL;
        g_vpack[vbase[v] + pv] = t | (s_sh[t] << 16);
    }
}

// ---------------------------------------------------------------------------
// VN update, z-quad per thread. Edge loop processed in chunks of 4 with
// split issue/consume passes -> 8 loads in flight. Integer accumulation is
// exact (messages are 2*q in [-15,15]).
// ---------------------------------------------------------------------------
__global__ __launch_bounds__(512, 2) void k_vn(const float* __restrict__ xa,
                                               float* __restrict__ out_prev,
                                               int write_out, int write_tot) {
    __shared__ __align__(16) float s[NV][68];    // padded transpose rows
    __shared__ int svptr[NV + 1];
    __shared__ int svpack[NE];
    const int tx = threadIdx.x;           // quad within tile (16)
    const int ty = threadIdx.y;           // n-group (32)
    const int tid = ty * 16 + tx;
    const int b = blockIdx.y;
    const int q0 = blockIdx.x * 16;       // quad tile base
    const int q = q0 + tx;
    const int z4 = q * 4;

    for (int i = tid; i <= NV; i += 512) svptr[i] = g_vnptr[i];
    for (int i = tid; i < NE; i += 512) svpack[i] = g_vpack[i];
    __syncthreads();

    const signed char* __restrict__ eq = g_extq + (size_t)b * (NE * ZL);
    float* __restrict__ tb = g_tot + (size_t)b * (NV * ZL);

    for (int n = ty; n < NV; n += 32) {
        float4 ch = ((const float4*)xa)[((size_t)b * NV + n) * ZW + q];
        int a0 = 0, a1 = 0, a2 = 0, a3 = 0;   // exact integer sums
        int j = svptr[n];
        const int j1 = svptr[n + 1];
        while (j < j1) {
            const int cnt = j1 - j;            // >=1
            unsigned ua[4], ub[4];
            int sh[4];
#pragma unroll
            for (int k = 0; k < 4; ++k) {
                if (k < cnt) {
                    const int pk = svpack[j + k];
                    int zc = z4 + (pk >> 16); if (zc >= ZL) zc -= ZL;
                    const unsigned* __restrict__ row =
                        (const unsigned*)(eq + (pk & 511) * ZL);
                    const int w0 = zc >> 2;
                    int w1 = w0 + 1; if (w1 == ZW) w1 = 0;
                    ua[k] = row[w0];
                    ub[k] = row[w1];
                    sh[k] = (zc & 3) * 8;
                }
            }
#pragma unroll
            for (int k = 0; k < 4; ++k) {
                if (k < cnt) {
                    const unsigned u = __funnelshift_r(ua[k], ub[k], sh[k]);
                    a0 += (int)(signed char)(u);
                    a1 += (int)(signed char)(u >> 8);
                    a2 += (int)(signed char)(u >> 16);
                    a3 += (int)(signed char)(u >> 24);
                }
            }
            j += 4;
        }
        ch.x += 0.5f * (float)a0;
        ch.y += 0.5f * (float)a1;
        ch.z += 0.5f * (float)a2;
        ch.w += 0.5f * (float)a3;
        if (write_tot) ((float4*)tb)[n * ZW + q] = ch;
        *(float4*)&s[n][tx * 4] = ch;
    }
    if (write_out) {
        __syncthreads();
        float4* __restrict__ dst = (float4*)(out_prev + ((size_t)b * ZL + q0 * 4) * NV);
        for (int f = tid; f < 64 * 17; f += 512) {
            const int zl = f / 17;
            const int n0 = (f - zl * 17) * 4;
            float4 o;
            o.x = s[n0 + 0][zl]; o.y = s[n0 + 1][zl];
            o.z = s[n0 + 2][zl]; o.w = s[n0 + 3][zl];
            dst[f] = o;
        }
    }
}

// ---------------------------------------------------------------------------
// CN update (min-sum, reference-exact tie semantics) + integer quantizer.
// One block per (CN, batch): 192 threads = 192 z-pairs = full ring. Edge
// metadata is uniform per block (8-entry shared arrays) -> address math is
// uniform_base + z. Pass-A batched loads (24 in flight). ext in {m1,m2} ->
// rounded ints precomputed per z-lane; sign = XOR of raw sign bits.
// ---------------------------------------------------------------------------
__global__ __launch_bounds__(192, 6) void k_cn(const float* __restrict__ cnw,
                                               const float* __restrict__ xa,
                                               int it, int first) {
    __shared__ int svn[8], ssh[8], seo[8];
    const int tid = threadIdx.x;
    const int c = blockIdx.x;
    const int b = blockIdx.y;
    if (tid < 8) {
        svn[tid] = g_cvn[c * 8 + tid];
        ssh[tid] = g_csh[c * 8 + tid];
        seo[tid] = g_ceo[c * 8 + tid];
    }
    __syncthreads();

    const int z2 = tid * 2;
    const float w = __ldg(&cnw[it]);
    const float w2m = fabsf(w + w);
    const unsigned wsb = __float_as_uint(w) & 0x80000000u;
    const float* __restrict__ tb =
        (first ? xa : (const float*)g_tot) + (size_t)b * (NV * ZL);
    signed char* __restrict__ eqz = g_extq + (size_t)b * (NE * ZL) + z2;

    // Pass A: batch all loads (16 tot floats + 8 state shorts in flight)
    float t0[8], t1[8];
    int es[8];
#pragma unroll
    for (int j = 0; j < 8; ++j) {
        int zv = z2 - ssh[j]; if (zv < 0) zv += ZL;
        const float* __restrict__ r = tb + svn[j];
        t0[j] = r[zv];
        int zn = zv + 1; if (zn == ZL) zn = 0;
        t1[j] = r[zn];
        es[j] = first ? 0 : (int)*(const short*)(eqz + seo[j]);
    }
    // Pass B: extrinsic beliefs, sign XOR, min1
    float v0[8], v1[8];
    unsigned s0 = wsb, s1 = wsb;          // running sign XOR (w sign folded)
    float m10 = 1e30f, m11 = 1e30f;
#pragma unroll
    for (int j = 0; j < 8; ++j) {
        const float c0 = 0.5f * (float)((signed char)(es[j]));
        const float c1 = 0.5f * (float)((signed char)(es[j] >> 8));
        const float a0 = fminf(fmaxf(t0[j] - c0, -20.f), 20.f);
        const float a1 = fminf(fmaxf(t1[j] - c1, -20.f), 20.f);
        v0[j] = a0; v1[j] = a1;
        s0 ^= __float_as_uint(a0);
        s1 ^= __float_as_uint(a1);
        m10 = fminf(m10, fabsf(a0));
        m11 = fminf(m11, fabsf(a1));
    }
    float m20 = 1e9f, m21 = 1e9f;         // BIG, matches reference when all tie
#pragma unroll
    for (int j = 0; j < 8; ++j) {
        float a;
        a = fabsf(v0[j]); if (a != m10) m20 = fminf(m20, a);
        a = fabsf(v1[j]); if (a != m11) m21 = fminf(m21, a);
    }
    // Precomputed quantized magnitudes (stored value = 2*q in [-15,15]):
    // __float2int_rn = round-half-even; clip-then-round == round-then-clip @15.
    const int i10 = __float2int_rn(fminf(w2m * m10, 15.f));
    const int i20 = __float2int_rn(fminf(w2m * m20, 15.f));
    const int i11 = __float2int_rn(fminf(w2m * m11, 15.f));
    const int i21 = __float2int_rn(fminf(w2m * m21, 15.f));
#pragma unroll
    for (int j = 0; j < 8; ++j) {
        int u, m, sel, b0, b1;
        u = (int)(s0 ^ __float_as_uint(v0[j])); m = u >> 31;
        sel = (fabsf(v0[j]) == m10) ? i20 : i10; b0 = (sel ^ m) - m;
        u = (int)(s1 ^ __float_as_uint(v1[j])); m = u >> 31;
        sel = (fabsf(v1[j]) == m11) ? i21 : i11; b1 = (sel ^ m) - m;
        *(short*)(eqz + seo[j]) = (short)((b0 & 0xff) | (b1 << 8));
    }
}

// ---------------------------------------------------------------------------
extern "C" void kernel_launch(void* const* d_in, const int* in_sizes, int n_in,
                              void* d_out, int out_size) {
    const float* xa  = (const float*)d_in[0];   // [B, N, Z] f32
    const float* cnw = (const float*)d_in[1];   // [ITERS] f32
    const int* evn   = (const int*)d_in[2];     // [E] i32
    const int* ecn   = (const int*)d_in[3];     // [E] i32
    const int* esh   = (const int*)d_in[4];     // [E] i32
    float* out = (float*)d_out;                 // [ITERS, B, Z, N] f32

    k_setup<<<1, 384>>>(evn, ecn, esh);

    dim3 blkV(16, 32);
    dim3 gV(6, BB);                 // 6 quad-tiles of 16 quads (64 z) x batch
    dim3 gC(MC, BB);                // one block per (CN, batch), 192 z-pairs

    for (int it = 0; it < ITERS; ++it) {
        // it==0 reads beliefs straight from xa (tot == xa), no priming k_vn.
        k_cn<<<gC, 192>>>(cnw, xa, it, it == 0);
        // VN pass of iteration it+1 writes out[it] (== marginalized output of
        // it); the last one needs no tot for a subsequent CN pass.
        k_vn<<<gV, blkV>>>(xa, out + (size_t)it * BB * ZL * NV, 1,
                           it != ITERS - 1);
    }
}

// round 11
// speedup vs baseline: 5.6048x; 1.0522x over previous
#include <cuda_runtime.h>

// Problem constants (fixed by this dataset instance)
#define ITERS 5
#define NV 68      // base VNs
#define MC 46      // base CNs
#define ZL 384     // lifting size
#define NE 368     // edges (= MC*8, regular degree-8 checks by construction)
#define BB 64      // batch
#define ZW (ZL/4)  // 96 words per edge row

// Persistent scratch (no allocations allowed)
__device__ __align__(16) signed char g_extq[BB * NE * ZL];    // quantized C2V, 2*q in [-15,15]
__device__ __align__(16) float       g_tot [BB * NV * 2 * ZL];// beliefs, DOUBLED rows [b][n][2*ZL]
// CN-ordered per-edge metadata (uniform per CN-block in k_cn)
__device__ int g_czo[NE];   // vn*2*ZL + (ZL - shift)  -> wrap-free gather base
__device__ int g_ceo[NE];   // e * ZL
// VN CSR for k_vn
__device__ int g_vnptr[NV + 1];
__device__ int g_vpack[NE]; // VN-order: e | shift<<16

// ---------------------------------------------------------------------------
// Setup: build CN-ordered metadata arrays and VN-CSR (deterministic).
// ---------------------------------------------------------------------------
__global__ void k_setup(const int* __restrict__ evn, const int* __restrict__ ecn,
                        const int* __restrict__ esh) {
    __shared__ int s_vn[NE], s_cn[NE], s_sh[NE];
    __shared__ int ccnt[MC], vcnt[NV];
    __shared__ int cbase[MC], vbase[NV];
    int t = threadIdx.x;
    if (t < NE) { s_vn[t] = evn[t]; s_cn[t] = ecn[t]; s_sh[t] = esh[t]; }
    if (t < MC) ccnt[t] = 0;
    if (t < NV) vcnt[t] = 0;
    __syncthreads();
    if (t < NE) { atomicAdd(&ccnt[s_cn[t]], 1); atomicAdd(&vcnt[s_vn[t]], 1); }
    __syncthreads();
    if (t == 0) {
        int run = 0;
        for (int c = 0; c < MC; ++c) { cbase[c] = run; run += ccnt[c]; }
        run = 0;
        for (int n = 0; n < NV; ++n) { vbase[n] = run; g_vnptr[n] = run; run += vcnt[n]; }
        g_vnptr[NV] = run;
    }
    __syncthreads();
    if (t < NE) {
        int c = s_cn[t], v = s_vn[t];
        int pc = 0, pv = 0;
        for (int e2 = 0; e2 < t; ++e2) {     // stable (e-ascending) position
            pc += (s_cn[e2] == c);
            pv += (s_vn[e2] == v);
        }
        const int pos = cbase[c] + pc;
        g_czo[pos] = v * (2 * ZL) + (ZL - s_sh[t]);
        g_ceo[pos] = t * ZL;
        g_vpack[vbase[v] + pv] = t | (s_sh[t] << 16);
    }
}

// ---------------------------------------------------------------------------
// Prime: tot = xa, written doubled (both row halves). One-shot before iter 0.
// ---------------------------------------------------------------------------
__global__ __launch_bounds__(512) void k_prime(const float* __restrict__ xa) {
    const int idx = blockIdx.x * 512 + threadIdx.x;   // over BB*NV*ZW quads
    if (idx >= BB * NV * ZW) return;
    const int row = idx / ZW;       // b*NV + n
    const int q = idx - row * ZW;
    const float4 v = ((const float4*)xa)[idx];
    float4* __restrict__ d = (float4*)g_tot + (size_t)row * (2 * ZW);
    d[q] = v;
    d[q + ZW] = v;
}

// ---------------------------------------------------------------------------
// VN update, z-quad per thread. Edge loop in chunks of 4 with split
// issue/consume passes (8 loads in flight). Integer accumulation is exact.
// Writes tot DOUBLED (float4 x2) and optionally out[it-1][b][z][n].
// ---------------------------------------------------------------------------
__global__ __launch_bounds__(512, 2) void k_vn(const float* __restrict__ xa,
                                               float* __restrict__ out_prev,
                                               int write_out, int write_tot) {
    __shared__ __align__(16) float s[NV][68];    // padded transpose rows
    __shared__ int svptr[NV + 1];
    __shared__ int svpack[NE];
    const int tx = threadIdx.x;           // quad within tile (16)
    const int ty = threadIdx.y;           // n-group (32)
    const int tid = ty * 16 + tx;
    const int b = blockIdx.y;
    const int q0 = blockIdx.x * 16;       // quad tile base
    const int q = q0 + tx;
    const int z4 = q * 4;

    for (int i = tid; i <= NV; i += 512) svptr[i] = g_vnptr[i];
    for (int i = tid; i < NE; i += 512) svpack[i] = g_vpack[i];
    __syncthreads();

    const signed char* __restrict__ eq = g_extq + (size_t)b * (NE * ZL);
    float* __restrict__ tb = g_tot + (size_t)b * (NV * 2 * ZL);

    for (int n = ty; n < NV; n += 32) {
        float4 ch = ((const float4*)xa)[((size_t)b * NV + n) * ZW + q];
        int a0 = 0, a1 = 0, a2 = 0, a3 = 0;   // exact integer sums
        int j = svptr[n];
        const int j1 = svptr[n + 1];
        while (j < j1) {
            const int cnt = j1 - j;            // >=1
            unsigned ua[4], ub[4];
            int sh[4];
#pragma unroll
            for (int k = 0; k < 4; ++k) {
                if (k < cnt) {
                    const int pk = svpack[j + k];
                    int zc = z4 + (pk >> 16); if (zc >= ZL) zc -= ZL;
                    const unsigned* __restrict__ row =
                        (const unsigned*)(eq + (pk & 511) * ZL);
                    const int w0 = zc >> 2;
                    int w1 = w0 + 1; if (w1 == ZW) w1 = 0;
                    ua[k] = row[w0];
                    ub[k] = row[w1];
                    sh[k] = (zc & 3) * 8;
                }
            }
#pragma unroll
            for (int k = 0; k < 4; ++k) {
                if (k < cnt) {
                    const unsigned u = __funnelshift_r(ua[k], ub[k], sh[k]);
                    a0 += (int)(signed char)(u);
                    a1 += (int)(signed char)(u >> 8);
                    a2 += (int)(signed char)(u >> 16);
                    a3 += (int)(signed char)(u >> 24);
                }
            }
            j += 4;
        }
        ch.x += 0.5f * (float)a0;
        ch.y += 0.5f * (float)a1;
        ch.z += 0.5f * (float)a2;
        ch.w += 0.5f * (float)a3;
        if (write_tot) {
            float4* __restrict__ tr = (float4*)tb + n * (2 * ZW);
            tr[q] = ch;
            tr[q + ZW] = ch;
        }
        *(float4*)&s[n][tx * 4] = ch;
    }
    if (write_out) {
        __syncthreads();
        float4* __restrict__ dst = (float4*)(out_prev + ((size_t)b * ZL + q0 * 4) * NV);
        for (int f = tid; f < 64 * 17; f += 512) {
            const int zl = f / 17;
            const int n0 = (f - zl * 17) * 4;
            float4 o;
            o.x = s[n0 + 0][zl]; o.y = s[n0 + 1][zl];
            o.z = s[n0 + 2][zl]; o.w = s[n0 + 3][zl];
            dst[f] = o;
        }
    }
}

// ---------------------------------------------------------------------------
// CN update (min-sum, reference-exact tie semantics) + LUT quantizer.
// One block per (CN, batch): 192 threads = 192 z-pairs. Doubled tot rows make
// the gather wrap-free: addr = uniform_zo + z2 (t1 via +1 immediate).
// Output pair = one byte_perm over per-lane LUTs {+m1,-m1,+m2,-m2}.
// ---------------------------------------------------------------------------
__global__ __launch_bounds__(192, 6) void k_cn(const float* __restrict__ cnw,
                                               int it, int first) {
    __shared__ int szo[8], seo[8];
    const int tid = threadIdx.x;
    const int c = blockIdx.x;
    const int b = blockIdx.y;
    if (tid < 8) {
        szo[tid] = g_czo[c * 8 + tid];
        seo[tid] = g_ceo[c * 8 + tid];
    }
    __syncthreads();

    const int z2 = tid * 2;
    const float w = __ldg(&cnw[it]);
    const float w2m = fabsf(w + w);
    const unsigned wsb = __float_as_uint(w) & 0x80000000u;
    const float* __restrict__ tbr = g_tot + (size_t)b * (NV * 2 * ZL);
    signed char* __restrict__ eqz = g_extq + (size_t)b * (NE * ZL) + z2;

    // Pass A: batch all loads (16 tot floats + 8 state shorts in flight)
    float t0[8], t1[8];
    int es[8];
#pragma unroll
    for (int j = 0; j < 8; ++j) {
        const int za = szo[j] + z2;        // wrap-free (doubled rows)
        t0[j] = tbr[za];
        t1[j] = tbr[za + 1];
        es[j] = first ? 0 : (int)*(const short*)(eqz + seo[j]);
    }
    // Pass B: extrinsic beliefs, sign XOR, min1
    float v0[8], v1[8];
    unsigned s0 = wsb, s1 = wsb;          // running sign XOR (w sign folded)
    float m10 = 1e30f, m11 = 1e30f;
#pragma unroll
    for (int j = 0; j < 8; ++j) {
        const float c0 = 0.5f * (float)((signed char)(es[j]));
        const float c1 = 0.5f * (float)((signed char)(es[j] >> 8));
        const float a0 = fminf(fmaxf(t0[j] - c0, -20.f), 20.f);
        const float a1 = fminf(fmaxf(t1[j] - c1, -20.f), 20.f);
        v0[j] = a0; v1[j] = a1;
        s0 ^= __float_as_uint(a0);
        s1 ^= __float_as_uint(a1);
        m10 = fminf(m10, fabsf(a0));
        m11 = fminf(m11, fabsf(a1));
    }
    float m20 = 1e9f, m21 = 1e9f;         // BIG, matches reference when all tie
#pragma unroll
    for (int j = 0; j < 8; ++j) {
        float a;
        a = fabsf(v0[j]); if (a != m10) m20 = fminf(m20, a);
        a = fabsf(v1[j]); if (a != m11) m21 = fminf(m21, a);
    }
    // Quantized magnitudes (stored value = 2*q in [-15,15]):
    // __float2int_rn = round-half-even; clip-then-round == round-then-clip @15.
    const int i10 = __float2int_rn(fminf(w2m * m10, 15.f));
    const int i20 = __float2int_rn(fminf(w2m * m20, 15.f));
    const int i11 = __float2int_rn(fminf(w2m * m11, 15.f));
    const int i21 = __float2int_rn(fminf(w2m * m21, 15.f));
    // Per-lane byte LUT: [ +m1, -m1, +m2, -m2 ]
    const unsigned lut0 = (unsigned)i10 | (((unsigned)(-i10) & 0xff) << 8)
                        | ((unsigned)i20 << 16) | (((unsigned)(-i20) & 0xff) << 24);
    const unsigned lut1 = (unsigned)i11 | (((unsigned)(-i11) & 0xff) << 8)
                        | ((unsigned)i21 << 16) | (((unsigned)(-i21) & 0xff) << 24);
#pragma unroll
    for (int j = 0; j < 8; ++j) {
        const unsigned u0 = s0 ^ __float_as_uint(v0[j]);
        const unsigned u1 = s1 ^ __float_as_uint(v1[j]);
        int idx0 = (int)(u0 >> 31);       // sign bit
        if (fabsf(v0[j]) == m10) idx0 |= 2;   // is-min -> use m2
        int idx1 = (int)(u1 >> 31) | 4;   // select from lut1
        if (fabsf(v1[j]) == m11) idx1 |= 2;
        const unsigned r = __byte_perm(lut0, lut1, (unsigned)(idx0 | (idx1 << 4)));
        *(short*)(eqz + seo[j]) = (short)r;
    }
}

// ---------------------------------------------------------------------------
extern "C" void kernel_launch(void* const* d_in, const int* in_sizes, int n_in,
                              void* d_out, int out_size) {
    const float* xa  = (const float*)d_in[0];   // [B, N, Z] f32
    const float* cnw = (const float*)d_in[1];   // [ITERS] f32
    const int* evn   = (const int*)d_in[2];     // [E] i32
    const int* ecn   = (const int*)d_in[3];     // [E] i32
    const int* esh   = (const int*)d_in[4];     // [E] i32
    float* out = (float*)d_out;                 // [ITERS, B, Z, N] f32

    k_setup<<<1, 384>>>(evn, ecn, esh);
    k_prime<<<(BB * NV * ZW + 511) / 512, 512>>>(xa);   // tot = xa (doubled rows)

    dim3 blkV(16, 32);
    dim3 gV(6, BB);                 // 6 quad-tiles of 16 quads (64 z) x batch
    dim3 gC(MC, BB);                // one block per (CN, batch), 192 z-pairs

    for (int it = 0; it < ITERS; ++it) {
        k_cn<<<gC, 192>>>(cnw, it, it == 0);
        // VN pass of iteration it+1 writes out[it] (== marginalized output of
        // it); the last one needs no tot for a subsequent CN pass.
        k_vn<<<gV, blkV>>>(xa, out + (size_t)it * BB * ZL * NV, 1,
                           it != ITERS - 1);
    }
}